// round 1
// baseline (speedup 1.0000x reference)
#include <cuda_runtime.h>
#include <math.h>

#define SQ   2048   // sequence length
#define HID  2048   // hidden size (also HK*KD)
#define NHK  16     // key heads
#define KDIM 128    // key dim
#define VDIM 256    // effective value dim per key head (VEFF)
#define NVD  4096   // HV*DV total value width
#define OUT_ELEMS  (SQ*HID)
#define SF_ELEMS   (NHK*KDIM*VDIM)

// ---------------- scratch (static device memory; no runtime allocs) ----------
__device__ float g_q   [SQ*HID];
__device__ float g_k   [SQ*HID];
__device__ float g_v   [SQ*NVD];
__device__ float g_qc  [SQ*HID];
__device__ float g_kc  [SQ*HID];
__device__ float g_gate[SQ*NHK];
__device__ float g_beta[SQ*NHK];
__device__ float g_attn[SQ*NVD];

// ---------------- generic C = A * B^T, fp32 ---------------------------------
// A: (M,K) row-major, B: (N,K) row-major, C: (M,N) row-major.
// 128x128 tile, BK=32, 256 threads, 8x8 microtile.
__global__ __launch_bounds__(256) void gemm_abt(const float* __restrict__ A,
                                                const float* __restrict__ B,
                                                float* __restrict__ C,
                                                int M, int N, int K) {
    __shared__ float As[32][132];
    __shared__ float Bs[32][132];
    const int bm = blockIdx.y * 128;
    const int bn = blockIdx.x * 128;
    const int t  = threadIdx.x;
    const int tx = t & 15, ty = t >> 4;
    const int lk = (t & 7) * 4;   // k offset for this thread's float4 loads
    const int lr = t >> 3;        // base row 0..31

    float acc[8][8];
#pragma unroll
    for (int i = 0; i < 8; ++i)
#pragma unroll
        for (int j = 0; j < 8; ++j) acc[i][j] = 0.f;

    for (int k0 = 0; k0 < K; k0 += 32) {
#pragma unroll
        for (int p = 0; p < 4; ++p) {
            int row = lr + 32 * p;
            float4 a = *(const float4*)&A[(size_t)(bm + row) * K + k0 + lk];
            As[lk + 0][row] = a.x; As[lk + 1][row] = a.y;
            As[lk + 2][row] = a.z; As[lk + 3][row] = a.w;
            float4 b = *(const float4*)&B[(size_t)(bn + row) * K + k0 + lk];
            Bs[lk + 0][row] = b.x; Bs[lk + 1][row] = b.y;
            Bs[lk + 2][row] = b.z; Bs[lk + 3][row] = b.w;
        }
        __syncthreads();
#pragma unroll 4
        for (int k = 0; k < 32; ++k) {
            float4 a0 = *(const float4*)&As[k][ty * 8];
            float4 a1 = *(const float4*)&As[k][ty * 8 + 4];
            float4 b0 = *(const float4*)&Bs[k][tx * 8];
            float4 b1 = *(const float4*)&Bs[k][tx * 8 + 4];
            float av[8] = {a0.x, a0.y, a0.z, a0.w, a1.x, a1.y, a1.z, a1.w};
            float bv[8] = {b0.x, b0.y, b0.z, b0.w, b1.x, b1.y, b1.z, b1.w};
#pragma unroll
            for (int i = 0; i < 8; ++i)
#pragma unroll
                for (int j = 0; j < 8; ++j) acc[i][j] += av[i] * bv[j];
        }
        __syncthreads();
    }
#pragma unroll
    for (int i = 0; i < 8; ++i) {
        float4 c0 = make_float4(acc[i][0], acc[i][1], acc[i][2], acc[i][3]);
        float4 c1 = make_float4(acc[i][4], acc[i][5], acc[i][6], acc[i][7]);
        size_t off = (size_t)(bm + ty * 8 + i) * N + bn + tx * 8;
        *(float4*)&C[off]     = c0;
        *(float4*)&C[off + 4] = c1;
    }
}

// ---------------- gate / beta: x @ W^T + b -> sigmoid ------------------------
__global__ __launch_bounds__(1024) void gates_kernel(const float* __restrict__ X,
        const float* __restrict__ Wg, const float* __restrict__ bg,
        const float* __restrict__ Wb, const float* __restrict__ bb,
        float* __restrict__ gate, float* __restrict__ beta) {
    __shared__ float xs[HID];
    const int s = blockIdx.x;
    for (int i = threadIdx.x; i < HID; i += 1024) xs[i] = X[(size_t)s * HID + i];
    __syncthreads();
    const int w = threadIdx.x >> 5, lane = threadIdx.x & 31;
    const float* row = (w < 16) ? (Wg + (size_t)w * HID) : (Wb + (size_t)(w - 16) * HID);
    float p = 0.f;
    for (int i = lane; i < HID; i += 32) p += xs[i] * row[i];
#pragma unroll
    for (int off = 16; off; off >>= 1) p += __shfl_xor_sync(0xffffffffu, p, off);
    if (lane == 0) {
        int hh = (w < 16) ? w : (w - 16);
        float bv = (w < 16) ? bg[hh] : bb[hh];
        float sv = 1.f / (1.f + expf(-(p + bv)));
        if (w < 16) gate[s * NHK + hh] = sv;
        else        beta[s * NHK + hh] = sv;
    }
}

// ---------------- grouped causal conv (+bias, silu) --------------------------
// y[s,o] = silu( bias[o] + sum_{i<128,tap<4} W[o,i,tap] * x[s-3+tap, g*128+i] )
// Implemented as 4 time-shifted per-group 64x64 GEMM tiles.
__global__ __launch_bounds__(256) void conv_silu(const float* __restrict__ X,
        const float* __restrict__ W, const float* __restrict__ bias,
        float* __restrict__ Y) {
    __shared__ float As[32][68];
    __shared__ float Bs[32][68];
    const int g  = blockIdx.z;          // group 0..15
    const int bn = blockIdx.y * 64;     // out-channel tile inside group (0 or 64)
    const int bm = blockIdx.x * 64;     // time tile
    const int t  = threadIdx.x;
    const int tx = t & 15, ty = t >> 4;
    const int lk = (t & 7) * 4;
    const int lr = t >> 3;

    float acc[4][4];
#pragma unroll
    for (int i = 0; i < 4; ++i)
#pragma unroll
        for (int j = 0; j < 4; ++j) acc[i][j] = 0.f;

    for (int tap = 0; tap < 4; ++tap) {
        for (int i0 = 0; i0 < 128; i0 += 32) {
#pragma unroll
            for (int p = 0; p < 2; ++p) {
                int m = lr + 32 * p;
                int s = bm + m - 3 + tap;
                float4 a = make_float4(0.f, 0.f, 0.f, 0.f);
                if (s >= 0)
                    a = *(const float4*)&X[(size_t)s * HID + g * 128 + i0 + lk];
                As[lk + 0][m] = a.x; As[lk + 1][m] = a.y;
                As[lk + 2][m] = a.z; As[lk + 3][m] = a.w;
                int o = g * 128 + bn + m;   // out channel for B-tile row m
                const float* wp = &W[(size_t)o * 512 + (size_t)(i0 + lk) * 4 + tap];
                Bs[lk + 0][m] = wp[0];  Bs[lk + 1][m] = wp[4];
                Bs[lk + 2][m] = wp[8];  Bs[lk + 3][m] = wp[12];
            }
            __syncthreads();
#pragma unroll 8
            for (int k = 0; k < 32; ++k) {
                float4 a = *(const float4*)&As[k][ty * 4];
                float4 b = *(const float4*)&Bs[k][tx * 4];
                float av[4] = {a.x, a.y, a.z, a.w};
                float bv[4] = {b.x, b.y, b.z, b.w};
#pragma unroll
                for (int i = 0; i < 4; ++i)
#pragma unroll
                    for (int j = 0; j < 4; ++j) acc[i][j] += av[i] * bv[j];
            }
            __syncthreads();
        }
    }
#pragma unroll
    for (int i = 0; i < 4; ++i)
#pragma unroll
        for (int j = 0; j < 4; ++j) {
            int s = bm + ty * 4 + i;
            int o = g * 128 + bn + tx * 4 + j;
            float yv = acc[i][j] + bias[o];
            yv = yv / (1.f + expf(-yv));     // silu
            Y[(size_t)s * HID + o] = yv;
        }
}

// ---------------- sequential gated scan --------------------------------------
// State per head: S[128(k), 256(v)]. Columns are independent:
//   S_t[:,c] = b_t * S_{t-1}[:,c] + k_t * v_t[c];  o_t[c] = g_t * (q_t . S_t[:,c])
// grid: 16 heads x 8 column-groups of 32 columns. 256 threads/CTA.
// Thread (rg = t%16, cg = t/16) owns rows {rg+16a, a<8} x cols {c0+2cg, c0+2cg+1}.
__global__ __launch_bounds__(256) void scan_kernel(const float* __restrict__ Q,
        const float* __restrict__ K, const float* __restrict__ V,
        const float* __restrict__ Beta, const float* __restrict__ Gate,
        float* __restrict__ O, float* __restrict__ Sf) {
    __shared__ float qs[32][128];
    __shared__ float ks[32][128];
    __shared__ float vs[32][32];
    __shared__ float bs[32], gs[32];
    const int h  = blockIdx.x >> 3;
    const int c0 = (blockIdx.x & 7) * 32;
    const int t  = threadIdx.x;
    const int rg = t & 15;
    const int cg = t >> 4;

    float S0[8], S1[8];
#pragma unroll
    for (int a = 0; a < 8; ++a) { S0[a] = 0.f; S1[a] = 0.f; }

    for (int s0 = 0; s0 < SQ; s0 += 32) {
        for (int idx = t; idx < 32 * 128; idx += 256) {
            int tt = idx >> 7, col = idx & 127;
            qs[tt][col] = Q[(size_t)(s0 + tt) * HID + h * 128 + col];
            ks[tt][col] = K[(size_t)(s0 + tt) * HID + h * 128 + col];
        }
        for (int idx = t; idx < 32 * 32; idx += 256) {
            int tt = idx >> 5, col = idx & 31;
            vs[tt][col] = V[(size_t)(s0 + tt) * NVD + h * 256 + c0 + col];
        }
        if (t < 32) {
            bs[t] = Beta[(s0 + t) * NHK + h];
            gs[t] = Gate[(s0 + t) * NHK + h];
        }
        __syncthreads();
        for (int tt = 0; tt < 32; ++tt) {
            float bt = bs[tt];
            float v0 = vs[tt][cg * 2 + 0];
            float v1 = vs[tt][cg * 2 + 1];
            float p0 = 0.f, p1 = 0.f;
#pragma unroll
            for (int a = 0; a < 8; ++a) {
                float kr = ks[tt][rg + 16 * a];
                float qr = qs[tt][rg + 16 * a];
                S0[a] = bt * S0[a] + kr * v0;
                S1[a] = bt * S1[a] + kr * v1;
                p0 += qr * S0[a];
                p1 += qr * S1[a];
            }
#pragma unroll
            for (int off = 8; off; off >>= 1) {
                p0 += __shfl_xor_sync(0xffffffffu, p0, off);
                p1 += __shfl_xor_sync(0xffffffffu, p1, off);
            }
            if (rg == 0) {
                float gt = gs[tt];
                size_t oo = (size_t)(s0 + tt) * NVD + h * 256 + c0 + cg * 2;
                O[oo]     = gt * p0;
                O[oo + 1] = gt * p1;
            }
        }
        __syncthreads();
    }
    if (Sf != nullptr) {
#pragma unroll
        for (int a = 0; a < 8; ++a) {
            size_t base = (size_t)h * KDIM * VDIM + (size_t)(rg + 16 * a) * VDIM
                        + c0 + cg * 2;
            Sf[base]     = S0[a];
            Sf[base + 1] = S1[a];
        }
    }
}

// ---------------- launch ------------------------------------------------------
extern "C" void kernel_launch(void* const* d_in, const int* in_sizes, int n_in,
                              void* d_out, int out_size) {
    const float* x   = (const float*)d_in[0];
    const float* Wq  = (const float*)d_in[1];
    const float* Wk  = (const float*)d_in[2];
    const float* Wv  = (const float*)d_in[3];
    const float* Wo  = (const float*)d_in[4];
    const float* Wqc = (const float*)d_in[5];
    const float* bqc = (const float*)d_in[6];
    const float* Wkc = (const float*)d_in[7];
    const float* bkc = (const float*)d_in[8];
    const float* Wg  = (const float*)d_in[9];
    const float* bg  = (const float*)d_in[10];
    const float* Wb  = (const float*)d_in[11];
    const float* bb  = (const float*)d_in[12];
    float* out = (float*)d_out;

    float *dq, *dk, *dv, *dqc, *dkc, *dgate, *dbeta, *dattn;
    cudaGetSymbolAddress((void**)&dq,    g_q);
    cudaGetSymbolAddress((void**)&dk,    g_k);
    cudaGetSymbolAddress((void**)&dv,    g_v);
    cudaGetSymbolAddress((void**)&dqc,   g_qc);
    cudaGetSymbolAddress((void**)&dkc,   g_kc);
    cudaGetSymbolAddress((void**)&dgate, g_gate);
    cudaGetSymbolAddress((void**)&dbeta, g_beta);
    cudaGetSymbolAddress((void**)&dattn, g_attn);

    dim3 blk(256);
    // projections
    gemm_abt<<<dim3(16, 16), blk>>>(x, Wq, dq, SQ, HID, HID);
    gemm_abt<<<dim3(16, 16), blk>>>(x, Wk, dk, SQ, HID, HID);
    gemm_abt<<<dim3(32, 16), blk>>>(x, Wv, dv, SQ, NVD, HID);
    // gates
    gates_kernel<<<SQ, 1024>>>(x, Wg, bg, Wb, bb, dgate, dbeta);
    // causal grouped conv + silu
    conv_silu<<<dim3(32, 2, 16), blk>>>(dq, Wqc, bqc, dqc);
    conv_silu<<<dim3(32, 2, 16), blk>>>(dk, Wkc, bkc, dkc);
    // recurrent scan (writes attention output and final state)
    float* Sf = (out_size >= OUT_ELEMS + SF_ELEMS) ? (out + OUT_ELEMS) : nullptr;
    scan_kernel<<<128, blk>>>(dqc, dkc, dv, dbeta, dgate, dattn, Sf);
    // output projection
    gemm_abt<<<dim3(16, 16), blk>>>(dattn, Wo, out, SQ, HID, NVD);
}

// round 4
// speedup vs baseline: 1.5657x; 1.5657x over previous
#include <cuda_runtime.h>
#include <cuda_bf16.h>
#include <math.h>
#include <cstdint>

#define SQ   2048
#define HID  2048
#define NHK  16
#define KDIM 128
#define VDIM 256
#define NVD  4096
#define OUT_ELEMS  (SQ*HID)
#define SF_ELEMS   (NHK*KDIM*VDIM)

// ---------------- scratch -----------------------------------------------------
__device__ __align__(256) float g_q   [SQ*HID];
__device__ __align__(256) float g_k   [SQ*HID];
__device__ __align__(256) float g_v   [SQ*NVD];
__device__ __align__(256) float g_qc  [SQ*HID];
__device__ __align__(256) float g_kc  [SQ*HID];
__device__ __align__(256) float g_gate[SQ*NHK];
__device__ __align__(256) float g_beta[SQ*NHK];
__device__ __align__(256) float g_attn[SQ*NVD];

__device__ __align__(256) __nv_bfloat16 g_xh [SQ*HID],  g_xl [SQ*HID];
__device__ __align__(256) __nv_bfloat16 g_wqh[HID*HID], g_wql[HID*HID];
__device__ __align__(256) __nv_bfloat16 g_wkh[HID*HID], g_wkl[HID*HID];
__device__ __align__(256) __nv_bfloat16 g_wvh[NVD*HID], g_wvl[NVD*HID];
__device__ __align__(256) __nv_bfloat16 g_woh[HID*NVD], g_wol[HID*NVD];
__device__ __align__(256) __nv_bfloat16 g_ah [SQ*NVD],  g_al [SQ*NVD];

// ---------------- PTX helpers --------------------------------------------------
__device__ __forceinline__ uint32_t smem_u32(const void* p) {
    uint32_t a;
    asm("{ .reg .u64 t; cvta.to.shared.u64 t, %1; cvt.u32.u64 %0, t; }" : "=r"(a) : "l"(p));
    return a;
}
__device__ __forceinline__ void cp16(uint32_t dst, const void* src) {
    asm volatile("cp.async.cg.shared.global [%0], [%1], 16;" :: "r"(dst), "l"(src));
}
#define CP_COMMIT() asm volatile("cp.async.commit_group;")
#define CP_WAIT(n)  asm volatile("cp.async.wait_group %0;" :: "n"(n))

__device__ __forceinline__ void ldsm_x4(uint32_t& r0, uint32_t& r1, uint32_t& r2,
                                        uint32_t& r3, uint32_t a) {
    asm volatile("ldmatrix.sync.aligned.m8n8.x4.shared.b16 {%0,%1,%2,%3}, [%4];"
                 : "=r"(r0), "=r"(r1), "=r"(r2), "=r"(r3) : "r"(a));
}
__device__ __forceinline__ void mma16816(float* d, const uint32_t* a, const uint32_t* b) {
    asm volatile(
        "mma.sync.aligned.m16n8k16.row.col.f32.bf16.bf16.f32 "
        "{%0,%1,%2,%3},{%4,%5,%6,%7},{%8,%9},{%0,%1,%2,%3};"
        : "+f"(d[0]), "+f"(d[1]), "+f"(d[2]), "+f"(d[3])
        : "r"(a[0]), "r"(a[1]), "r"(a[2]), "r"(a[3]), "r"(b[0]), "r"(b[1]));
}

// ---------------- split float -> bf16 hi/lo -----------------------------------
__global__ __launch_bounds__(256) void split_kernel(const float2* __restrict__ X,
        __nv_bfloat162* __restrict__ H, __nv_bfloat162* __restrict__ L, int n2) {
    int i = blockIdx.x * 256 + threadIdx.x;
    if (i >= n2) return;
    float2 x = X[i];
    __nv_bfloat16 hx = __float2bfloat16(x.x), hy = __float2bfloat16(x.y);
    float rx = x.x - __bfloat162float(hx);
    float ry = x.y - __bfloat162float(hy);
    __nv_bfloat162 h; h.x = hx; h.y = hy;
    __nv_bfloat162 l; l.x = __float2bfloat16(rx); l.y = __float2bfloat16(ry);
    H[i] = h; L[i] = l;
}

// ---------------- bf16 split GEMM via mma.sync: C = A * B^T -------------------
// A (M,K), B (N,K) row-major, hi/lo split. Tile 128x128, BK=32, 8 warps (2x4).
#define ROWB  80u          // 32 bf16 padded to 40 elems = 80 bytes, 16B aligned
#define MATB  (128u*ROWB)  // 10240 bytes per matrix tile
#define STAGEB (4u*MATB)   // Ah, Al, Bh, Bl
#define GSMEM  (2u*STAGEB) // 81920

__device__ __forceinline__ void ld_stage(uint32_t st,
        const __nv_bfloat16* __restrict__ Ah, const __nv_bfloat16* __restrict__ Al,
        const __nv_bfloat16* __restrict__ Bh, const __nv_bfloat16* __restrict__ Bl,
        int bm, int bn, int k0, int K, int t) {
#pragma unroll
    for (int i = 0; i < 8; ++i) {
        int idx = t + i * 256;         // 0..2047
        int mat = idx >> 9;            // 0:Ah 1:Al 2:Bh 3:Bl
        int j   = idx & 511;
        int row = j >> 2, c = j & 3;   // row 0..127, 16B chunk 0..3
        const __nv_bfloat16* base = (mat == 0) ? Ah : (mat == 1) ? Al
                                   : (mat == 2) ? Bh : Bl;
        int grow = ((mat < 2) ? bm : bn) + row;
        cp16(st + mat * MATB + row * ROWB + c * 16,
             base + (size_t)grow * K + k0 + c * 8);
    }
}

__global__ __launch_bounds__(256, 1) void gemm_mma(
        const __nv_bfloat16* __restrict__ Ah, const __nv_bfloat16* __restrict__ Al,
        const __nv_bfloat16* __restrict__ Bh, const __nv_bfloat16* __restrict__ Bl,
        float* __restrict__ C, int M, int N, int K) {
    extern __shared__ char smem[];
    uint32_t sb = smem_u32(smem);
    const int t = threadIdx.x, wid = t >> 5, lane = t & 31;
    const int wm = wid >> 2, wn = wid & 3;       // 2 x 4 warp grid
    const int bm = blockIdx.y * 128, bn = blockIdx.x * 128;

    float acc[4][4][4];
#pragma unroll
    for (int mt = 0; mt < 4; ++mt)
#pragma unroll
        for (int nt = 0; nt < 4; ++nt)
#pragma unroll
            for (int r = 0; r < 4; ++r) acc[mt][nt][r] = 0.f;

    // ldmatrix address components (byte offsets within a matrix tile)
    const uint32_t rowA = wm * 64 + (lane & 15);
    const uint32_t colA = (uint32_t)(lane >> 4) << 4;          // k-halves: +8 elems
    const uint32_t rowB = wn * 32 + ((uint32_t)(lane >> 4) << 3) + (lane & 7);
    const uint32_t colB = (uint32_t)((lane >> 3) & 1) << 4;

    const int nch = K / 32;
    ld_stage(sb, Ah, Al, Bh, Bl, bm, bn, 0, K, t);
    CP_COMMIT();

    for (int c = 0; c < nch; ++c) {
        uint32_t cur = (c & 1) ? STAGEB : 0u;
        if (c + 1 < nch) {
            uint32_t nxt = cur ^ STAGEB;
            ld_stage(sb + nxt, Ah, Al, Bh, Bl, bm, bn, (c + 1) * 32, K, t);
            CP_COMMIT();
            CP_WAIT(1);
        } else {
            CP_WAIT(0);
        }
        __syncthreads();

        uint32_t aAh = sb + cur + rowA * ROWB + colA;
        uint32_t aAl = aAh + MATB;
        uint32_t aBh = sb + cur + 2 * MATB + rowB * ROWB + colB;
        uint32_t aBl = aBh + MATB;

#pragma unroll
        for (int kh = 0; kh < 2; ++kh) {          // two k16 steps (byte +32)
            uint32_t ah[4][4], al[4][4], bh[4][2], bl[4][2];
#pragma unroll
            for (int mt = 0; mt < 4; ++mt) {
                ldsm_x4(ah[mt][0], ah[mt][1], ah[mt][2], ah[mt][3],
                        aAh + mt * (16 * ROWB) + kh * 32);
                ldsm_x4(al[mt][0], al[mt][1], al[mt][2], al[mt][3],
                        aAl + mt * (16 * ROWB) + kh * 32);
            }
#pragma unroll
            for (int p = 0; p < 2; ++p) {         // each x4 covers 2 n-tiles
                ldsm_x4(bh[2*p][0], bh[2*p][1], bh[2*p+1][0], bh[2*p+1][1],
                        aBh + p * (16 * ROWB) + kh * 32);
                ldsm_x4(bl[2*p][0], bl[2*p][1], bl[2*p+1][0], bl[2*p+1][1],
                        aBl + p * (16 * ROWB) + kh * 32);
            }
#pragma unroll
            for (int mt = 0; mt < 4; ++mt)
#pragma unroll
                for (int nt = 0; nt < 4; ++nt)
                    mma16816(acc[mt][nt], ah[mt], bh[nt]);
#pragma unroll
            for (int mt = 0; mt < 4; ++mt)
#pragma unroll
                for (int nt = 0; nt < 4; ++nt)
                    mma16816(acc[mt][nt], ah[mt], bl[nt]);
#pragma unroll
            for (int mt = 0; mt < 4; ++mt)
#pragma unroll
                for (int nt = 0; nt < 4; ++nt)
                    mma16816(acc[mt][nt], al[mt], bh[nt]);
        }
        __syncthreads();
    }

    // epilogue: direct fp32 stores
    const int r0 = bm + wm * 64 + (lane >> 2);
    const int cc = bn + wn * 32 + (lane & 3) * 2;
#pragma unroll
    for (int mt = 0; mt < 4; ++mt)
#pragma unroll
        for (int nt = 0; nt < 4; ++nt) {
            int rr = r0 + mt * 16;
            int cl = cc + nt * 8;
            *(float2*)&C[(size_t)rr * N + cl]       = make_float2(acc[mt][nt][0], acc[mt][nt][1]);
            *(float2*)&C[(size_t)(rr + 8) * N + cl] = make_float2(acc[mt][nt][2], acc[mt][nt][3]);
        }
}

// ---------------- gate / beta -------------------------------------------------
__global__ __launch_bounds__(1024) void gates_kernel(const float* __restrict__ X,
        const float* __restrict__ Wg, const float* __restrict__ bg,
        const float* __restrict__ Wb, const float* __restrict__ bb,
        float* __restrict__ gate, float* __restrict__ beta) {
    __shared__ float xs[HID];
    const int s = blockIdx.x;
    for (int i = threadIdx.x; i < HID; i += 1024) xs[i] = X[(size_t)s * HID + i];
    __syncthreads();
    const int w = threadIdx.x >> 5, lane = threadIdx.x & 31;
    const float* row = (w < 16) ? (Wg + (size_t)w * HID) : (Wb + (size_t)(w - 16) * HID);
    float p = 0.f;
    for (int i = lane; i < HID; i += 32) p += xs[i] * row[i];
#pragma unroll
    for (int off = 16; off; off >>= 1) p += __shfl_xor_sync(0xffffffffu, p, off);
    if (lane == 0) {
        int hh = (w < 16) ? w : (w - 16);
        float bv = (w < 16) ? bg[hh] : bb[hh];
        float sv = 1.f / (1.f + expf(-(p + bv)));
        if (w < 16) gate[s * NHK + hh] = sv;
        else        beta[s * NHK + hh] = sv;
    }
}

// ---------------- grouped causal conv + silu ----------------------------------
__global__ __launch_bounds__(256) void conv_silu(const float* __restrict__ X,
        const float* __restrict__ W, const float* __restrict__ bias,
        float* __restrict__ Y) {
    __shared__ float As[32][68];
    __shared__ float Bs[32][68];
    const int g  = blockIdx.z;
    const int bn = blockIdx.y * 64;
    const int bm = blockIdx.x * 64;
    const int t  = threadIdx.x;
    const int tx = t & 15, ty = t >> 4;
    const int lk = (t & 7) * 4;
    const int lr = t >> 3;

    float acc[4][4];
#pragma unroll
    for (int i = 0; i < 4; ++i)
#pragma unroll
        for (int j = 0; j < 4; ++j) acc[i][j] = 0.f;

    for (int tap = 0; tap < 4; ++tap) {
        for (int i0 = 0; i0 < 128; i0 += 32) {
#pragma unroll
            for (int p = 0; p < 2; ++p) {
                int m = lr + 32 * p;
                int s = bm + m - 3 + tap;
                float4 a = make_float4(0.f, 0.f, 0.f, 0.f);
                if (s >= 0)
                    a = *(const float4*)&X[(size_t)s * HID + g * 128 + i0 + lk];
                As[lk + 0][m] = a.x; As[lk + 1][m] = a.y;
                As[lk + 2][m] = a.z; As[lk + 3][m] = a.w;
                int o = g * 128 + bn + m;
                const float* wp = &W[(size_t)o * 512 + (size_t)(i0 + lk) * 4 + tap];
                Bs[lk + 0][m] = wp[0];  Bs[lk + 1][m] = wp[4];
                Bs[lk + 2][m] = wp[8];  Bs[lk + 3][m] = wp[12];
            }
            __syncthreads();
#pragma unroll 8
            for (int k = 0; k < 32; ++k) {
                float4 a = *(const float4*)&As[k][ty * 4];
                float4 b = *(const float4*)&Bs[k][tx * 4];
                float av[4] = {a.x, a.y, a.z, a.w};
                float bv[4] = {b.x, b.y, b.z, b.w};
#pragma unroll
                for (int i = 0; i < 4; ++i)
#pragma unroll
                    for (int j = 0; j < 4; ++j) acc[i][j] += av[i] * bv[j];
            }
            __syncthreads();
        }
    }
#pragma unroll
    for (int i = 0; i < 4; ++i)
#pragma unroll
        for (int j = 0; j < 4; ++j) {
            int s = bm + ty * 4 + i;
            int o = g * 128 + bn + tx * 4 + j;
            float yv = acc[i][j] + bias[o];
            yv = yv / (1.f + expf(-yv));
            Y[(size_t)s * HID + o] = yv;
        }
}

// ---------------- sequential gated scan ---------------------------------------
__global__ __launch_bounds__(256) void scan_kernel(const float* __restrict__ Q,
        const float* __restrict__ K, const float* __restrict__ V,
        const float* __restrict__ Beta, const float* __restrict__ Gate,
        float* __restrict__ O, float* __restrict__ Sf) {
    __shared__ float qs[32][128];
    __shared__ float ks[32][128];
    __shared__ float vs[32][32];
    __shared__ float bs[32], gs[32];
    const int h  = blockIdx.x >> 3;
    const int c0 = (blockIdx.x & 7) * 32;
    const int t  = threadIdx.x;
    const int rg = t & 15;
    const int cg = t >> 4;

    float S0[8], S1[8];
#pragma unroll
    for (int a = 0; a < 8; ++a) { S0[a] = 0.f; S1[a] = 0.f; }

    for (int s0 = 0; s0 < SQ; s0 += 32) {
        for (int idx = t; idx < 32 * 128; idx += 256) {
            int tt = idx >> 7, col = idx & 127;
            qs[tt][col] = Q[(size_t)(s0 + tt) * HID + h * 128 + col];
            ks[tt][col] = K[(size_t)(s0 + tt) * HID + h * 128 + col];
        }
        for (int idx = t; idx < 32 * 32; idx += 256) {
            int tt = idx >> 5, col = idx & 31;
            vs[tt][col] = V[(size_t)(s0 + tt) * NVD + h * 256 + c0 + col];
        }
        if (t < 32) {
            bs[t] = Beta[(s0 + t) * NHK + h];
            gs[t] = Gate[(s0 + t) * NHK + h];
        }
        __syncthreads();
        for (int tt = 0; tt < 32; ++tt) {
            float bt = bs[tt];
            float v0 = vs[tt][cg * 2 + 0];
            float v1 = vs[tt][cg * 2 + 1];
            float p0 = 0.f, p1 = 0.f;
#pragma unroll
            for (int a = 0; a < 8; ++a) {
                float kr = ks[tt][rg + 16 * a];
                float qr = qs[tt][rg + 16 * a];
                S0[a] = bt * S0[a] + kr * v0;
                S1[a] = bt * S1[a] + kr * v1;
                p0 += qr * S0[a];
                p1 += qr * S1[a];
            }
#pragma unroll
            for (int off = 8; off; off >>= 1) {
                p0 += __shfl_xor_sync(0xffffffffu, p0, off);
                p1 += __shfl_xor_sync(0xffffffffu, p1, off);
            }
            if (rg == 0) {
                float gt = gs[tt];
                size_t oo = (size_t)(s0 + tt) * NVD + h * 256 + c0 + cg * 2;
                O[oo]     = gt * p0;
                O[oo + 1] = gt * p1;
            }
        }
        __syncthreads();
    }
    if (Sf != nullptr) {
#pragma unroll
        for (int a = 0; a < 8; ++a) {
            size_t base = (size_t)h * KDIM * VDIM + (size_t)(rg + 16 * a) * VDIM
                        + c0 + cg * 2;
            Sf[base]     = S0[a];
            Sf[base + 1] = S1[a];
        }
    }
}

// ---------------- launch ------------------------------------------------------
extern "C" void kernel_launch(void* const* d_in, const int* in_sizes, int n_in,
                              void* d_out, int out_size) {
    const float* x   = (const float*)d_in[0];
    const float* Wq  = (const float*)d_in[1];
    const float* Wk  = (const float*)d_in[2];
    const float* Wv  = (const float*)d_in[3];
    const float* Wo  = (const float*)d_in[4];
    const float* Wqc = (const float*)d_in[5];
    const float* bqc = (const float*)d_in[6];
    const float* Wkc = (const float*)d_in[7];
    const float* bkc = (const float*)d_in[8];
    const float* Wg  = (const float*)d_in[9];
    const float* bg  = (const float*)d_in[10];
    const float* Wb  = (const float*)d_in[11];
    const float* bb  = (const float*)d_in[12];
    float* out = (float*)d_out;

    float *dq, *dk, *dv, *dqc, *dkc, *dgate, *dbeta, *dattn;
    cudaGetSymbolAddress((void**)&dq,    g_q);
    cudaGetSymbolAddress((void**)&dk,    g_k);
    cudaGetSymbolAddress((void**)&dv,    g_v);
    cudaGetSymbolAddress((void**)&dqc,   g_qc);
    cudaGetSymbolAddress((void**)&dkc,   g_kc);
    cudaGetSymbolAddress((void**)&dgate, g_gate);
    cudaGetSymbolAddress((void**)&dbeta, g_beta);
    cudaGetSymbolAddress((void**)&dattn, g_attn);

    __nv_bfloat16 *xh, *xl, *wqh, *wql, *wkh, *wkl, *wvh, *wvl, *woh, *wol, *ah, *al;
    cudaGetSymbolAddress((void**)&xh,  g_xh);  cudaGetSymbolAddress((void**)&xl,  g_xl);
    cudaGetSymbolAddress((void**)&wqh, g_wqh); cudaGetSymbolAddress((void**)&wql, g_wql);
    cudaGetSymbolAddress((void**)&wkh, g_wkh); cudaGetSymbolAddress((void**)&wkl, g_wkl);
    cudaGetSymbolAddress((void**)&wvh, g_wvh); cudaGetSymbolAddress((void**)&wvl, g_wvl);
    cudaGetSymbolAddress((void**)&woh, g_woh); cudaGetSymbolAddress((void**)&wol, g_wol);
    cudaGetSymbolAddress((void**)&ah,  g_ah);  cudaGetSymbolAddress((void**)&al,  g_al);

    cudaFuncSetAttribute(gemm_mma, cudaFuncAttributeMaxDynamicSharedMemorySize, GSMEM);

    dim3 blk(256);
    // splits
    {
        int n2;
        n2 = SQ*HID/2;  split_kernel<<<(n2+255)/256, 256>>>((const float2*)x,  (__nv_bfloat162*)xh,  (__nv_bfloat162*)xl,  n2);
        n2 = HID*HID/2; split_kernel<<<(n2+255)/256, 256>>>((const float2*)Wq, (__nv_bfloat162*)wqh, (__nv_bfloat162*)wql, n2);
        n2 = HID*HID/2; split_kernel<<<(n2+255)/256, 256>>>((const float2*)Wk, (__nv_bfloat162*)wkh, (__nv_bfloat162*)wkl, n2);
        n2 = NVD*HID/2; split_kernel<<<(n2+255)/256, 256>>>((const float2*)Wv, (__nv_bfloat162*)wvh, (__nv_bfloat162*)wvl, n2);
        n2 = HID*NVD/2; split_kernel<<<(n2+255)/256, 256>>>((const float2*)Wo, (__nv_bfloat162*)woh, (__nv_bfloat162*)wol, n2);
    }
    // projections (tensor cores, split-bf16)
    gemm_mma<<<dim3(HID/128, SQ/128), blk, GSMEM>>>(xh, xl, wqh, wql, dq, SQ, HID, HID);
    gemm_mma<<<dim3(HID/128, SQ/128), blk, GSMEM>>>(xh, xl, wkh, wkl, dk, SQ, HID, HID);
    gemm_mma<<<dim3(NVD/128, SQ/128), blk, GSMEM>>>(xh, xl, wvh, wvl, dv, SQ, NVD, HID);
    // gates
    gates_kernel<<<SQ, 1024>>>(x, Wg, bg, Wb, bb, dgate, dbeta);
    // causal grouped conv + silu
    conv_silu<<<dim3(32, 2, 16), blk>>>(dq, Wqc, bqc, dqc);
    conv_silu<<<dim3(32, 2, 16), blk>>>(dk, Wkc, bkc, dkc);
    // recurrent scan
    float* Sf = (out_size >= OUT_ELEMS + SF_ELEMS) ? (out + OUT_ELEMS) : nullptr;
    scan_kernel<<<128, blk>>>(dqc, dkc, dv, dbeta, dgate, dattn, Sf);
    // output projection
    {
        int n2 = SQ*NVD/2;
        split_kernel<<<(n2+255)/256, 256>>>((const float2*)dattn, (__nv_bfloat162*)ah, (__nv_bfloat162*)al, n2);
    }
    gemm_mma<<<dim3(HID/128, SQ/128), blk, GSMEM>>>(ah, al, woh, wol, out, SQ, HID, NVD);
}

// round 5
// speedup vs baseline: 1.7862x; 1.1409x over previous
#include <cuda_runtime.h>
#include <cuda_bf16.h>
#include <math.h>
#include <cstdint>

#define SQ   2048
#define HID  2048
#define NHK  16
#define KDIM 128
#define VDIM 256
#define NVD  4096
#define OUT_ELEMS  (SQ*HID)
#define SF_ELEMS   (NHK*KDIM*VDIM)

// ---------------- scratch -----------------------------------------------------
__device__ __align__(256) float g_q   [SQ*HID];
__device__ __align__(256) float g_k   [SQ*HID];
__device__ __align__(256) float g_v   [SQ*NVD];
__device__ __align__(256) float g_qc  [SQ*HID];
__device__ __align__(256) float g_kc  [SQ*HID];
__device__ __align__(256) float g_gate[SQ*NHK];
__device__ __align__(256) float g_beta[SQ*NHK];
__device__ __align__(256) float g_attn[SQ*NVD];

__device__ __align__(256) __nv_bfloat16 g_xh [SQ*HID],  g_xl [SQ*HID];
__device__ __align__(256) __nv_bfloat16 g_wqh[HID*HID], g_wql[HID*HID];
__device__ __align__(256) __nv_bfloat16 g_wkh[HID*HID], g_wkl[HID*HID];
__device__ __align__(256) __nv_bfloat16 g_wvh[NVD*HID], g_wvl[NVD*HID];
__device__ __align__(256) __nv_bfloat16 g_woh[HID*NVD], g_wol[HID*NVD];
__device__ __align__(256) __nv_bfloat16 g_ah [SQ*NVD],  g_al [SQ*NVD];
// conv-stage splits + reshaped conv weights
__device__ __align__(256) __nv_bfloat16 g_qph[SQ*HID],  g_qpl[SQ*HID];
__device__ __align__(256) __nv_bfloat16 g_kph[SQ*HID],  g_kpl[SQ*HID];
__device__ __align__(256) __nv_bfloat16 g_cqh[HID*512], g_cql[HID*512];
__device__ __align__(256) __nv_bfloat16 g_ckh[HID*512], g_ckl[HID*512];

// ---------------- PTX helpers --------------------------------------------------
__device__ __forceinline__ uint32_t smem_u32(const void* p) {
    uint32_t a;
    asm("{ .reg .u64 t; cvta.to.shared.u64 t, %1; cvt.u32.u64 %0, t; }" : "=r"(a) : "l"(p));
    return a;
}
__device__ __forceinline__ void cp16(uint32_t dst, const void* src) {
    asm volatile("cp.async.cg.shared.global [%0], [%1], 16;" :: "r"(dst), "l"(src));
}
#define CP_COMMIT() asm volatile("cp.async.commit_group;")
#define CP_WAIT(n)  asm volatile("cp.async.wait_group %0;" :: "n"(n))

__device__ __forceinline__ void ldsm_x4(uint32_t& r0, uint32_t& r1, uint32_t& r2,
                                        uint32_t& r3, uint32_t a) {
    asm volatile("ldmatrix.sync.aligned.m8n8.x4.shared.b16 {%0,%1,%2,%3}, [%4];"
                 : "=r"(r0), "=r"(r1), "=r"(r2), "=r"(r3) : "r"(a));
}
__device__ __forceinline__ void mma16816(float* d, const uint32_t* a, const uint32_t* b) {
    asm volatile(
        "mma.sync.aligned.m16n8k16.row.col.f32.bf16.bf16.f32 "
        "{%0,%1,%2,%3},{%4,%5,%6,%7},{%8,%9},{%0,%1,%2,%3};"
        : "+f"(d[0]), "+f"(d[1]), "+f"(d[2]), "+f"(d[3])
        : "r"(a[0]), "r"(a[1]), "r"(a[2]), "r"(a[3]), "r"(b[0]), "r"(b[1]));
}

// ---------------- fused split kernels -----------------------------------------
__device__ __forceinline__ void split_one(const float2* X, __nv_bfloat162* H,
                                          __nv_bfloat162* L, int i) {
    float2 x = X[i];
    __nv_bfloat16 hx = __float2bfloat16(x.x), hy = __float2bfloat16(x.y);
    float rx = x.x - __bfloat162float(hx);
    float ry = x.y - __bfloat162float(hy);
    __nv_bfloat162 h; h.x = hx; h.y = hy;
    __nv_bfloat162 l; l.x = __float2bfloat16(rx); l.y = __float2bfloat16(ry);
    H[i] = h; L[i] = l;
}

// blocks: [0,8192) x | [8192,16384) wq | [16384,24576) wk | [24576,40960) wv | [40960,57344) wo
__global__ __launch_bounds__(256) void split_all(
        const float2* x,  __nv_bfloat162* xh,  __nv_bfloat162* xl,
        const float2* wq, __nv_bfloat162* wqh, __nv_bfloat162* wql,
        const float2* wk, __nv_bfloat162* wkh, __nv_bfloat162* wkl,
        const float2* wv, __nv_bfloat162* wvh, __nv_bfloat162* wvl,
        const float2* wo, __nv_bfloat162* woh, __nv_bfloat162* wol) {
    int b = blockIdx.x;
    if (b < 8192)       split_one(x,  xh,  xl,  (b)         * 256 + threadIdx.x);
    else if (b < 16384) split_one(wq, wqh, wql, (b - 8192)  * 256 + threadIdx.x);
    else if (b < 24576) split_one(wk, wkh, wkl, (b - 16384) * 256 + threadIdx.x);
    else if (b < 40960) split_one(wv, wvh, wvl, (b - 24576) * 256 + threadIdx.x);
    else                split_one(wo, woh, wol, (b - 40960) * 256 + threadIdx.x);
}

__global__ __launch_bounds__(256) void split_qk(
        const float2* q, __nv_bfloat162* qh, __nv_bfloat162* ql,
        const float2* k, __nv_bfloat162* kh, __nv_bfloat162* kl) {
    int b = blockIdx.x;
    if (b < 8192) split_one(q, qh, ql, b * 256 + threadIdx.x);
    else          split_one(k, kh, kl, (b - 8192) * 256 + threadIdx.x);
}

__global__ __launch_bounds__(256) void split_simple(const float2* __restrict__ X,
        __nv_bfloat162* __restrict__ H, __nv_bfloat162* __restrict__ L, int n2) {
    int i = blockIdx.x * 256 + threadIdx.x;
    if (i >= n2) return;
    split_one(X, H, L, i);
}

// conv weight reshape + split: out[o*512 + tap*128 + i] = in[o*512 + i*4 + tap]
__global__ __launch_bounds__(256) void convw_reshape(
        const float* __restrict__ Wq, __nv_bfloat16* __restrict__ Qh, __nv_bfloat16* __restrict__ Ql,
        const float* __restrict__ Wk, __nv_bfloat16* __restrict__ Kh, __nv_bfloat16* __restrict__ Kl) {
    int b = blockIdx.x;
    const float* W = (b < 4096) ? Wq : Wk;
    __nv_bfloat16* H = (b < 4096) ? Qh : Kh;
    __nv_bfloat16* L = (b < 4096) ? Ql : Kl;
    int e = ((b < 4096) ? b : (b - 4096)) * 256 + threadIdx.x;
    int o = e >> 9, kk = e & 511;
    int tap = kk >> 7, i = kk & 127;
    float v = W[o * 512 + i * 4 + tap];
    __nv_bfloat16 h = __float2bfloat16(v);
    H[e] = h;
    L[e] = __float2bfloat16(v - __bfloat162float(h));
}

// ---------------- bf16 split GEMM via mma.sync: C = A * B^T -------------------
#define ROWB  80u
#define MATB  (128u*ROWB)
#define STAGEB (4u*MATB)
#define GSMEM  (2u*STAGEB)

__device__ __forceinline__ void ld_stage(uint32_t st,
        const __nv_bfloat16* __restrict__ Ah, const __nv_bfloat16* __restrict__ Al,
        const __nv_bfloat16* __restrict__ Bh, const __nv_bfloat16* __restrict__ Bl,
        int bm, int bn, int k0, int K, int t) {
#pragma unroll
    for (int i = 0; i < 8; ++i) {
        int idx = t + i * 256;
        int mat = idx >> 9;
        int j   = idx & 511;
        int row = j >> 2, c = j & 3;
        const __nv_bfloat16* base = (mat == 0) ? Ah : (mat == 1) ? Al
                                   : (mat == 2) ? Bh : Bl;
        int grow = ((mat < 2) ? bm : bn) + row;
        cp16(st + mat * MATB + row * ROWB + c * 16,
             base + (size_t)grow * K + k0 + c * 8);
    }
}

__global__ __launch_bounds__(256, 1) void gemm_mma(
        const __nv_bfloat16* __restrict__ Ah, const __nv_bfloat16* __restrict__ Al,
        const __nv_bfloat16* __restrict__ Bh, const __nv_bfloat16* __restrict__ Bl,
        float* __restrict__ C, int M, int N, int K) {
    extern __shared__ char smem[];
    uint32_t sb = smem_u32(smem);
    const int t = threadIdx.x, wid = t >> 5, lane = t & 31;
    const int wm = wid >> 2, wn = wid & 3;
    const int bm = blockIdx.y * 128, bn = blockIdx.x * 128;

    float acc[4][4][4];
#pragma unroll
    for (int mt = 0; mt < 4; ++mt)
#pragma unroll
        for (int nt = 0; nt < 4; ++nt)
#pragma unroll
            for (int r = 0; r < 4; ++r) acc[mt][nt][r] = 0.f;

    const uint32_t rowA = wm * 64 + (lane & 15);
    const uint32_t colA = (uint32_t)(lane >> 4) << 4;
    const uint32_t rowB = wn * 32 + ((uint32_t)(lane >> 4) << 3) + (lane & 7);
    const uint32_t colB = (uint32_t)((lane >> 3) & 1) << 4;

    const int nch = K / 32;
    ld_stage(sb, Ah, Al, Bh, Bl, bm, bn, 0, K, t);
    CP_COMMIT();

    for (int c = 0; c < nch; ++c) {
        uint32_t cur = (c & 1) ? STAGEB : 0u;
        if (c + 1 < nch) {
            uint32_t nxt = cur ^ STAGEB;
            ld_stage(sb + nxt, Ah, Al, Bh, Bl, bm, bn, (c + 1) * 32, K, t);
            CP_COMMIT();
            CP_WAIT(1);
        } else {
            CP_WAIT(0);
        }
        __syncthreads();

        uint32_t aAh = sb + cur + rowA * ROWB + colA;
        uint32_t aAl = aAh + MATB;
        uint32_t aBh = sb + cur + 2 * MATB + rowB * ROWB + colB;
        uint32_t aBl = aBh + MATB;

#pragma unroll
        for (int kh = 0; kh < 2; ++kh) {
            uint32_t ah[4][4], al[4][4], bh[4][2], bl[4][2];
#pragma unroll
            for (int mt = 0; mt < 4; ++mt) {
                ldsm_x4(ah[mt][0], ah[mt][1], ah[mt][2], ah[mt][3],
                        aAh + mt * (16 * ROWB) + kh * 32);
                ldsm_x4(al[mt][0], al[mt][1], al[mt][2], al[mt][3],
                        aAl + mt * (16 * ROWB) + kh * 32);
            }
#pragma unroll
            for (int p = 0; p < 2; ++p) {
                ldsm_x4(bh[2*p][0], bh[2*p][1], bh[2*p+1][0], bh[2*p+1][1],
                        aBh + p * (16 * ROWB) + kh * 32);
                ldsm_x4(bl[2*p][0], bl[2*p][1], bl[2*p+1][0], bl[2*p+1][1],
                        aBl + p * (16 * ROWB) + kh * 32);
            }
#pragma unroll
            for (int mt = 0; mt < 4; ++mt)
#pragma unroll
                for (int nt = 0; nt < 4; ++nt)
                    mma16816(acc[mt][nt], ah[mt], bh[nt]);
#pragma unroll
            for (int mt = 0; mt < 4; ++mt)
#pragma unroll
                for (int nt = 0; nt < 4; ++nt)
                    mma16816(acc[mt][nt], ah[mt], bl[nt]);
#pragma unroll
            for (int mt = 0; mt < 4; ++mt)
#pragma unroll
                for (int nt = 0; nt < 4; ++nt)
                    mma16816(acc[mt][nt], al[mt], bh[nt]);
        }
        __syncthreads();
    }

    const int r0 = bm + wm * 64 + (lane >> 2);
    const int cc = bn + wn * 32 + (lane & 3) * 2;
#pragma unroll
    for (int mt = 0; mt < 4; ++mt)
#pragma unroll
        for (int nt = 0; nt < 4; ++nt) {
            int rr = r0 + mt * 16;
            int cl = cc + nt * 8;
            *(float2*)&C[(size_t)rr * N + cl]       = make_float2(acc[mt][nt][0], acc[mt][nt][1]);
            *(float2*)&C[(size_t)(rr + 8) * N + cl] = make_float2(acc[mt][nt][2], acc[mt][nt][3]);
        }
}

// ---------------- conv via split-bf16 mma -------------------------------------
// Per group g: Y[s, g*128+o] = silu(bias + sum_{kk<512} A[s,kk] * B[o,kk]),
// A[s, tap*128+i] = X[s-3+tap, g*128+i], B = reshaped conv weight (2048x512).
// grid: (g=16, mtile=16, conv=2), 256 threads, K=512 -> 16 chunks of 32.
__global__ __launch_bounds__(256, 1) void conv_mma(
        const __nv_bfloat16* __restrict__ Qh, const __nv_bfloat16* __restrict__ Ql,
        const __nv_bfloat16* __restrict__ Kh, const __nv_bfloat16* __restrict__ Kl,
        const __nv_bfloat16* __restrict__ WQh, const __nv_bfloat16* __restrict__ WQl,
        const __nv_bfloat16* __restrict__ WKh, const __nv_bfloat16* __restrict__ WKl,
        const float* __restrict__ bq, const float* __restrict__ bk,
        float* __restrict__ Yq, float* __restrict__ Yk) {
    extern __shared__ char smem[];
    uint32_t sb = smem_u32(smem);
    const int t = threadIdx.x, wid = t >> 5, lane = t & 31;
    const int wm = wid >> 2, wn = wid & 3;
    const int g  = blockIdx.x;
    const int bm = blockIdx.y * 128;
    const int cz = blockIdx.z;
    const __nv_bfloat16* Xh = cz ? Kh : Qh;
    const __nv_bfloat16* Xl = cz ? Kl : Ql;
    const __nv_bfloat16* Bh = cz ? WKh : WQh;
    const __nv_bfloat16* Bl = cz ? WKl : WQl;
    const float* bias = cz ? bk : bq;
    float* Y = cz ? Yk : Yq;

    float acc[4][4][4];
#pragma unroll
    for (int mt = 0; mt < 4; ++mt)
#pragma unroll
        for (int nt = 0; nt < 4; ++nt)
#pragma unroll
            for (int r = 0; r < 4; ++r) acc[mt][nt][r] = 0.f;

    const uint32_t rowA = wm * 64 + (lane & 15);
    const uint32_t colA = (uint32_t)(lane >> 4) << 4;
    const uint32_t rowB = wn * 32 + ((uint32_t)(lane >> 4) << 3) + (lane & 7);
    const uint32_t colB = (uint32_t)((lane >> 3) & 1) << 4;

    // stage loader: chunk k0 covers cols [k0,k0+32) of the virtual K=512
    auto load_chunk = [&](uint32_t st, int k0) {
        int tap = k0 >> 7, i0 = k0 & 127;
#pragma unroll
        for (int i = 0; i < 8; ++i) {
            int idx = t + i * 256;
            int mat = idx >> 9;
            int j   = idx & 511;
            int row = j >> 2, c = j & 3;
            uint32_t dst = st + mat * MATB + row * ROWB + c * 16;
            if (mat < 2) {
                int s = bm + row - 3 + tap;
                const __nv_bfloat16* base = (mat == 0) ? Xh : Xl;
                if (s >= 0)
                    cp16(dst, base + (size_t)s * HID + g * 128 + i0 + c * 8);
                else
                    *(uint4*)(smem + (dst - sb)) = make_uint4(0, 0, 0, 0);
            } else {
                const __nv_bfloat16* base = (mat == 2) ? Bh : Bl;
                cp16(dst, base + (size_t)(g * 128 + row) * 512 + k0 + c * 8);
            }
        }
    };

    load_chunk(sb, 0);
    CP_COMMIT();
    for (int c = 0; c < 16; ++c) {
        uint32_t cur = (c & 1) ? STAGEB : 0u;
        if (c + 1 < 16) {
            load_chunk(sb + (cur ^ STAGEB), (c + 1) * 32);
            CP_COMMIT();
            CP_WAIT(1);
        } else {
            CP_WAIT(0);
        }
        __syncthreads();

        uint32_t aAh = sb + cur + rowA * ROWB + colA;
        uint32_t aAl = aAh + MATB;
        uint32_t aBh = sb + cur + 2 * MATB + rowB * ROWB + colB;
        uint32_t aBl = aBh + MATB;
#pragma unroll
        for (int kh = 0; kh < 2; ++kh) {
            uint32_t ah[4][4], al[4][4], bh[4][2], bl[4][2];
#pragma unroll
            for (int mt = 0; mt < 4; ++mt) {
                ldsm_x4(ah[mt][0], ah[mt][1], ah[mt][2], ah[mt][3],
                        aAh + mt * (16 * ROWB) + kh * 32);
                ldsm_x4(al[mt][0], al[mt][1], al[mt][2], al[mt][3],
                        aAl + mt * (16 * ROWB) + kh * 32);
            }
#pragma unroll
            for (int p = 0; p < 2; ++p) {
                ldsm_x4(bh[2*p][0], bh[2*p][1], bh[2*p+1][0], bh[2*p+1][1],
                        aBh + p * (16 * ROWB) + kh * 32);
                ldsm_x4(bl[2*p][0], bl[2*p][1], bl[2*p+1][0], bl[2*p+1][1],
                        aBl + p * (16 * ROWB) + kh * 32);
            }
#pragma unroll
            for (int mt = 0; mt < 4; ++mt)
#pragma unroll
                for (int nt = 0; nt < 4; ++nt)
                    mma16816(acc[mt][nt], ah[mt], bh[nt]);
#pragma unroll
            for (int mt = 0; mt < 4; ++mt)
#pragma unroll
                for (int nt = 0; nt < 4; ++nt)
                    mma16816(acc[mt][nt], ah[mt], bl[nt]);
#pragma unroll
            for (int mt = 0; mt < 4; ++mt)
#pragma unroll
                for (int nt = 0; nt < 4; ++nt)
                    mma16816(acc[mt][nt], al[mt], bh[nt]);
        }
        __syncthreads();
    }

    const int r0 = bm + wm * 64 + (lane >> 2);
    const int c0 = wn * 32 + (lane & 3) * 2;
#pragma unroll
    for (int mt = 0; mt < 4; ++mt)
#pragma unroll
        for (int nt = 0; nt < 4; ++nt) {
            int cl = c0 + nt * 8;
            float b0 = bias[g * 128 + cl], b1 = bias[g * 128 + cl + 1];
#pragma unroll
            for (int half = 0; half < 2; ++half) {
                int rr = r0 + mt * 16 + half * 8;
                float y0 = acc[mt][nt][half * 2 + 0] + b0;
                float y1 = acc[mt][nt][half * 2 + 1] + b1;
                y0 = y0 / (1.f + expf(-y0));
                y1 = y1 / (1.f + expf(-y1));
                *(float2*)&Y[(size_t)rr * HID + g * 128 + cl] = make_float2(y0, y1);
            }
        }
}

// ---------------- gate / beta -------------------------------------------------
__global__ __launch_bounds__(1024) void gates_kernel(const float* __restrict__ X,
        const float* __restrict__ Wg, const float* __restrict__ bg,
        const float* __restrict__ Wb, const float* __restrict__ bb,
        float* __restrict__ gate, float* __restrict__ beta) {
    __shared__ float xs[HID];
    const int s = blockIdx.x;
    for (int i = threadIdx.x; i < HID; i += 1024) xs[i] = X[(size_t)s * HID + i];
    __syncthreads();
    const int w = threadIdx.x >> 5, lane = threadIdx.x & 31;
    const float* row = (w < 16) ? (Wg + (size_t)w * HID) : (Wb + (size_t)(w - 16) * HID);
    float p = 0.f;
    for (int i = lane; i < HID; i += 32) p += xs[i] * row[i];
#pragma unroll
    for (int off = 16; off; off >>= 1) p += __shfl_xor_sync(0xffffffffu, p, off);
    if (lane == 0) {
        int hh = (w < 16) ? w : (w - 16);
        float bv = (w < 16) ? bg[hh] : bb[hh];
        float sv = 1.f / (1.f + expf(-(p + bv)));
        if (w < 16) gate[s * NHK + hh] = sv;
        else        beta[s * NHK + hh] = sv;
    }
}

// ---------------- sequential gated scan ---------------------------------------
__global__ __launch_bounds__(256) void scan_kernel(const float* __restrict__ Q,
        const float* __restrict__ K, const float* __restrict__ V,
        const float* __restrict__ Beta, const float* __restrict__ Gate,
        float* __restrict__ O, float* __restrict__ Sf) {
    __shared__ float qs[32][128];
    __shared__ float ks[32][128];
    __shared__ float vs[32][32];
    __shared__ float bs[32], gs[32];
    const int h  = blockIdx.x >> 3;
    const int c0 = (blockIdx.x & 7) * 32;
    const int t  = threadIdx.x;
    const int rg = t & 15;
    const int cg = t >> 4;

    float S0[8], S1[8];
#pragma unroll
    for (int a = 0; a < 8; ++a) { S0[a] = 0.f; S1[a] = 0.f; }

    for (int s0 = 0; s0 < SQ; s0 += 32) {
        for (int idx = t; idx < 32 * 128; idx += 256) {
            int tt = idx >> 7, col = idx & 127;
            qs[tt][col] = Q[(size_t)(s0 + tt) * HID + h * 128 + col];
            ks[tt][col] = K[(size_t)(s0 + tt) * HID + h * 128 + col];
        }
        for (int idx = t; idx < 32 * 32; idx += 256) {
            int tt = idx >> 5, col = idx & 31;
            vs[tt][col] = V[(size_t)(s0 + tt) * NVD + h * 256 + c0 + col];
        }
        if (t < 32) {
            bs[t] = Beta[(s0 + t) * NHK + h];
            gs[t] = Gate[(s0 + t) * NHK + h];
        }
        __syncthreads();
        for (int tt = 0; tt < 32; ++tt) {
            float bt = bs[tt];
            float v0 = vs[tt][cg * 2 + 0];
            float v1 = vs[tt][cg * 2 + 1];
            float p0 = 0.f, p1 = 0.f;
#pragma unroll
            for (int a = 0; a < 8; ++a) {
                float kr = ks[tt][rg + 16 * a];
                float qr = qs[tt][rg + 16 * a];
                S0[a] = bt * S0[a] + kr * v0;
                S1[a] = bt * S1[a] + kr * v1;
                p0 += qr * S0[a];
                p1 += qr * S1[a];
            }
#pragma unroll
            for (int off = 8; off; off >>= 1) {
                p0 += __shfl_xor_sync(0xffffffffu, p0, off);
                p1 += __shfl_xor_sync(0xffffffffu, p1, off);
            }
            if (rg == 0) {
                float gt = gs[tt];
                size_t oo = (size_t)(s0 + tt) * NVD + h * 256 + c0 + cg * 2;
                O[oo]     = gt * p0;
                O[oo + 1] = gt * p1;
            }
        }
        __syncthreads();
    }
    if (Sf != nullptr) {
#pragma unroll
        for (int a = 0; a < 8; ++a) {
            size_t base = (size_t)h * KDIM * VDIM + (size_t)(rg + 16 * a) * VDIM
                        + c0 + cg * 2;
            Sf[base]     = S0[a];
            Sf[base + 1] = S1[a];
        }
    }
}

// ---------------- launch ------------------------------------------------------
extern "C" void kernel_launch(void* const* d_in, const int* in_sizes, int n_in,
                              void* d_out, int out_size) {
    const float* x   = (const float*)d_in[0];
    const float* Wq  = (const float*)d_in[1];
    const float* Wk  = (const float*)d_in[2];
    const float* Wv  = (const float*)d_in[3];
    const float* Wo  = (const float*)d_in[4];
    const float* Wqc = (const float*)d_in[5];
    const float* bqc = (const float*)d_in[6];
    const float* Wkc = (const float*)d_in[7];
    const float* bkc = (const float*)d_in[8];
    const float* Wg  = (const float*)d_in[9];
    const float* bg  = (const float*)d_in[10];
    const float* Wb  = (const float*)d_in[11];
    const float* bb  = (const float*)d_in[12];
    float* out = (float*)d_out;

    float *dq, *dk, *dv, *dqc, *dkc, *dgate, *dbeta, *dattn;
    cudaGetSymbolAddress((void**)&dq,    g_q);
    cudaGetSymbolAddress((void**)&dk,    g_k);
    cudaGetSymbolAddress((void**)&dv,    g_v);
    cudaGetSymbolAddress((void**)&dqc,   g_qc);
    cudaGetSymbolAddress((void**)&dkc,   g_kc);
    cudaGetSymbolAddress((void**)&dgate, g_gate);
    cudaGetSymbolAddress((void**)&dbeta, g_beta);
    cudaGetSymbolAddress((void**)&dattn, g_attn);

    __nv_bfloat16 *xh, *xl, *wqh, *wql, *wkh, *wkl, *wvh, *wvl, *woh, *wol, *ah, *al;
    __nv_bfloat16 *qph, *qpl, *kph, *kpl, *cqh, *cql, *ckh, *ckl;
    cudaGetSymbolAddress((void**)&xh,  g_xh);  cudaGetSymbolAddress((void**)&xl,  g_xl);
    cudaGetSymbolAddress((void**)&wqh, g_wqh); cudaGetSymbolAddress((void**)&wql, g_wql);
    cudaGetSymbolAddress((void**)&wkh, g_wkh); cudaGetSymbolAddress((void**)&wkl, g_wkl);
    cudaGetSymbolAddress((void**)&wvh, g_wvh); cudaGetSymbolAddress((void**)&wvl, g_wvl);
    cudaGetSymbolAddress((void**)&woh, g_woh); cudaGetSymbolAddress((void**)&wol, g_wol);
    cudaGetSymbolAddress((void**)&ah,  g_ah);  cudaGetSymbolAddress((void**)&al,  g_al);
    cudaGetSymbolAddress((void**)&qph, g_qph); cudaGetSymbolAddress((void**)&qpl, g_qpl);
    cudaGetSymbolAddress((void**)&kph, g_kph); cudaGetSymbolAddress((void**)&kpl, g_kpl);
    cudaGetSymbolAddress((void**)&cqh, g_cqh); cudaGetSymbolAddress((void**)&cql, g_cql);
    cudaGetSymbolAddress((void**)&ckh, g_ckh); cudaGetSymbolAddress((void**)&ckl, g_ckl);

    cudaFuncSetAttribute(gemm_mma, cudaFuncAttributeMaxDynamicSharedMemorySize, GSMEM);
    cudaFuncSetAttribute(conv_mma, cudaFuncAttributeMaxDynamicSharedMemorySize, GSMEM);

    dim3 blk(256);
    // 0: all input splits (x + 4 weights) in one launch
    split_all<<<57344, blk>>>(
        (const float2*)x,  (__nv_bfloat162*)xh,  (__nv_bfloat162*)xl,
        (const float2*)Wq, (__nv_bfloat162*)wqh, (__nv_bfloat162*)wql,
        (const float2*)Wk, (__nv_bfloat162*)wkh, (__nv_bfloat162*)wkl,
        (const float2*)Wv, (__nv_bfloat162*)wvh, (__nv_bfloat162*)wvl,
        (const float2*)Wo, (__nv_bfloat162*)woh, (__nv_bfloat162*)wol);
    // 1: conv weight reshape + split (both convs)
    convw_reshape<<<8192, blk>>>(Wqc, cqh, cql, Wkc, ckh, ckl);
    // 2: gates
    gates_kernel<<<SQ, 1024>>>(x, Wg, bg, Wb, bb, dgate, dbeta);
    // 3-5: projections (launch 5 = gemm_v is profiled by ncu -s 5 -c 1)
    gemm_mma<<<dim3(HID/128, SQ/128), blk, GSMEM>>>(xh, xl, wqh, wql, dq, SQ, HID, HID);
    gemm_mma<<<dim3(HID/128, SQ/128), blk, GSMEM>>>(xh, xl, wkh, wkl, dk, SQ, HID, HID);
    gemm_mma<<<dim3(NVD/128, SQ/128), blk, GSMEM>>>(xh, xl, wvh, wvl, dv, SQ, NVD, HID);
    // 6: split q,k for conv
    split_qk<<<16384, blk>>>((const float2*)dq, (__nv_bfloat162*)qph, (__nv_bfloat162*)qpl,
                             (const float2*)dk, (__nv_bfloat162*)kph, (__nv_bfloat162*)kpl);
    // 7: both convs on tensor cores
    conv_mma<<<dim3(16, 16, 2), blk, GSMEM>>>(qph, qpl, kph, kpl,
                                              cqh, cql, ckh, ckl,
                                              bqc, bkc, dqc, dkc);
    // 8: recurrent scan
    float* Sf = (out_size >= OUT_ELEMS + SF_ELEMS) ? (out + OUT_ELEMS) : nullptr;
    scan_kernel<<<128, blk>>>(dqc, dkc, dv, dbeta, dgate, dattn, Sf);
    // 9: split attn
    split_simple<<<SQ*NVD/2/256, blk>>>((const float2*)dattn, (__nv_bfloat162*)ah,
                                        (__nv_bfloat162*)al, SQ*NVD/2);
    // 10: output projection
    gemm_mma<<<dim3(HID/128, SQ/128), blk, GSMEM>>>(ah, al, woh, wol, out, SQ, HID, NVD);
}

// round 6
// speedup vs baseline: 1.9672x; 1.1014x over previous
#include <cuda_runtime.h>
#include <cuda_bf16.h>
#include <math.h>
#include <cstdint>

#define SQ   2048
#define HID  2048
#define NHK  16
#define KDIM 128
#define VDIM 256
#define NVD  4096
#define OUT_ELEMS  (SQ*HID)
#define SF_ELEMS   (NHK*KDIM*VDIM)

// ---------------- scratch -----------------------------------------------------
__device__ __align__(256) float g_v   [SQ*NVD];
__device__ __align__(256) float g_qc  [SQ*HID];
__device__ __align__(256) float g_kc  [SQ*HID];
__device__ __align__(256) float g_gate[SQ*NHK];
__device__ __align__(256) float g_beta[SQ*NHK];

__device__ __align__(256) __nv_bfloat16 g_xh [SQ*HID],  g_xl [SQ*HID];
__device__ __align__(256) __nv_bfloat16 g_wqh[HID*HID], g_wql[HID*HID];
__device__ __align__(256) __nv_bfloat16 g_wkh[HID*HID], g_wkl[HID*HID];
__device__ __align__(256) __nv_bfloat16 g_wvh[NVD*HID], g_wvl[NVD*HID];
__device__ __align__(256) __nv_bfloat16 g_woh[HID*NVD], g_wol[HID*NVD];
__device__ __align__(256) __nv_bfloat16 g_ah [SQ*NVD],  g_al [SQ*NVD];
__device__ __align__(256) __nv_bfloat16 g_qph[SQ*HID],  g_qpl[SQ*HID];
__device__ __align__(256) __nv_bfloat16 g_kph[SQ*HID],  g_kpl[SQ*HID];
__device__ __align__(256) __nv_bfloat16 g_cqh[HID*512], g_cql[HID*512];
__device__ __align__(256) __nv_bfloat16 g_ckh[HID*512], g_ckl[HID*512];

// ---------------- PTX helpers --------------------------------------------------
__device__ __forceinline__ uint32_t smem_u32(const void* p) {
    uint32_t a;
    asm("{ .reg .u64 t; cvta.to.shared.u64 t, %1; cvt.u32.u64 %0, t; }" : "=r"(a) : "l"(p));
    return a;
}
__device__ __forceinline__ void cp16(uint32_t dst, const void* src) {
    asm volatile("cp.async.cg.shared.global [%0], [%1], 16;" :: "r"(dst), "l"(src));
}
#define CP_COMMIT() asm volatile("cp.async.commit_group;")
#define CP_WAIT(n)  asm volatile("cp.async.wait_group %0;" :: "n"(n))

__device__ __forceinline__ void ldsm_x4(uint32_t& r0, uint32_t& r1, uint32_t& r2,
                                        uint32_t& r3, uint32_t a) {
    asm volatile("ldmatrix.sync.aligned.m8n8.x4.shared.b16 {%0,%1,%2,%3}, [%4];"
                 : "=r"(r0), "=r"(r1), "=r"(r2), "=r"(r3) : "r"(a));
}
__device__ __forceinline__ void mma16816(float* d, const uint32_t* a, const uint32_t* b) {
    asm volatile(
        "mma.sync.aligned.m16n8k16.row.col.f32.bf16.bf16.f32 "
        "{%0,%1,%2,%3},{%4,%5,%6,%7},{%8,%9},{%0,%1,%2,%3};"
        : "+f"(d[0]), "+f"(d[1]), "+f"(d[2]), "+f"(d[3])
        : "r"(a[0]), "r"(a[1]), "r"(a[2]), "r"(a[3]), "r"(b[0]), "r"(b[1]));
}

// ---------------- split kernels -----------------------------------------------
__device__ __forceinline__ void split_one(const float2* X, __nv_bfloat162* H,
                                          __nv_bfloat162* L, int i) {
    float2 x = X[i];
    __nv_bfloat16 hx = __float2bfloat16(x.x), hy = __float2bfloat16(x.y);
    float rx = x.x - __bfloat162float(hx);
    float ry = x.y - __bfloat162float(hy);
    __nv_bfloat162 h; h.x = hx; h.y = hy;
    __nv_bfloat162 l; l.x = __float2bfloat16(rx); l.y = __float2bfloat16(ry);
    H[i] = h; L[i] = l;
}

__global__ __launch_bounds__(256) void split_all(
        const float2* x,  __nv_bfloat162* xh,  __nv_bfloat162* xl,
        const float2* wq, __nv_bfloat162* wqh, __nv_bfloat162* wql,
        const float2* wk, __nv_bfloat162* wkh, __nv_bfloat162* wkl,
        const float2* wv, __nv_bfloat162* wvh, __nv_bfloat162* wvl,
        const float2* wo, __nv_bfloat162* woh, __nv_bfloat162* wol) {
    int b = blockIdx.x;
    if (b < 8192)       split_one(x,  xh,  xl,  (b)         * 256 + threadIdx.x);
    else if (b < 16384) split_one(wq, wqh, wql, (b - 8192)  * 256 + threadIdx.x);
    else if (b < 24576) split_one(wk, wkh, wkl, (b - 16384) * 256 + threadIdx.x);
    else if (b < 40960) split_one(wv, wvh, wvl, (b - 24576) * 256 + threadIdx.x);
    else                split_one(wo, woh, wol, (b - 40960) * 256 + threadIdx.x);
}

__global__ __launch_bounds__(256) void convw_reshape(
        const float* __restrict__ Wq, __nv_bfloat16* __restrict__ Qh, __nv_bfloat16* __restrict__ Ql,
        const float* __restrict__ Wk, __nv_bfloat16* __restrict__ Kh, __nv_bfloat16* __restrict__ Kl) {
    int b = blockIdx.x;
    const float* W = (b < 4096) ? Wq : Wk;
    __nv_bfloat16* H = (b < 4096) ? Qh : Kh;
    __nv_bfloat16* L = (b < 4096) ? Ql : Kl;
    int e = ((b < 4096) ? b : (b - 4096)) * 256 + threadIdx.x;
    int o = e >> 9, kk = e & 511;
    int tap = kk >> 7, i = kk & 127;
    float v = W[o * 512 + i * 4 + tap];
    __nv_bfloat16 h = __float2bfloat16(v);
    H[e] = h;
    L[e] = __float2bfloat16(v - __bfloat162float(h));
}

// ---------------- bf16 split GEMM via mma.sync: C = A * B^T -------------------
#define ROWB  80u
#define MATB  (128u*ROWB)
#define STAGEB (4u*MATB)
#define GSMEM  (2u*STAGEB)

__device__ __forceinline__ void ld_stage(uint32_t st,
        const __nv_bfloat16* __restrict__ Ah, const __nv_bfloat16* __restrict__ Al,
        const __nv_bfloat16* __restrict__ Bh, const __nv_bfloat16* __restrict__ Bl,
        int bm, int bn, int k0, int K, int t) {
#pragma unroll
    for (int i = 0; i < 8; ++i) {
        int idx = t + i * 256;
        int mat = idx >> 9;
        int j   = idx & 511;
        int row = j >> 2, c = j & 3;
        const __nv_bfloat16* base = (mat == 0) ? Ah : (mat == 1) ? Al
                                   : (mat == 2) ? Bh : Bl;
        int grow = ((mat < 2) ? bm : bn) + row;
        cp16(st + mat * MATB + row * ROWB + c * 16,
             base + (size_t)grow * K + k0 + c * 8);
    }
}

// out_mode 0: fp32 C. out_mode 1: split bf16 (Ch, Cl).
__global__ __launch_bounds__(256, 2) void gemm_mma(
        const __nv_bfloat16* __restrict__ Ah, const __nv_bfloat16* __restrict__ Al,
        const __nv_bfloat16* __restrict__ Bh, const __nv_bfloat16* __restrict__ Bl,
        float* __restrict__ C, __nv_bfloat16* __restrict__ Ch,
        __nv_bfloat16* __restrict__ Cl, int M, int N, int K, int out_mode) {
    extern __shared__ char smem[];
    uint32_t sb = smem_u32(smem);
    const int t = threadIdx.x, wid = t >> 5, lane = t & 31;
    const int wm = wid >> 2, wn = wid & 3;
    const int bm = blockIdx.y * 128, bn = blockIdx.x * 128;

    float acc[4][4][4];
#pragma unroll
    for (int mt = 0; mt < 4; ++mt)
#pragma unroll
        for (int nt = 0; nt < 4; ++nt)
#pragma unroll
            for (int r = 0; r < 4; ++r) acc[mt][nt][r] = 0.f;

    const uint32_t rowA = wm * 64 + (lane & 15);
    const uint32_t colA = (uint32_t)(lane >> 4) << 4;
    const uint32_t rowB = wn * 32 + ((uint32_t)(lane >> 4) << 3) + (lane & 7);
    const uint32_t colB = (uint32_t)((lane >> 3) & 1) << 4;

    const int nch = K / 32;
    ld_stage(sb, Ah, Al, Bh, Bl, bm, bn, 0, K, t);
    CP_COMMIT();

    for (int c = 0; c < nch; ++c) {
        uint32_t cur = (c & 1) ? STAGEB : 0u;
        if (c + 1 < nch) {
            uint32_t nxt = cur ^ STAGEB;
            ld_stage(sb + nxt, Ah, Al, Bh, Bl, bm, bn, (c + 1) * 32, K, t);
            CP_COMMIT();
            CP_WAIT(1);
        } else {
            CP_WAIT(0);
        }
        __syncthreads();

        uint32_t aAh = sb + cur + rowA * ROWB + colA;
        uint32_t aAl = aAh + MATB;
        uint32_t aBh = sb + cur + 2 * MATB + rowB * ROWB + colB;
        uint32_t aBl = aBh + MATB;

#pragma unroll
        for (int kh = 0; kh < 2; ++kh) {
            uint32_t ah[4][4], al[4][4], b[4][2];
#pragma unroll
            for (int mt = 0; mt < 4; ++mt) {
                ldsm_x4(ah[mt][0], ah[mt][1], ah[mt][2], ah[mt][3],
                        aAh + mt * (16 * ROWB) + kh * 32);
                ldsm_x4(al[mt][0], al[mt][1], al[mt][2], al[mt][3],
                        aAl + mt * (16 * ROWB) + kh * 32);
            }
            // Bh pass: Ah*Bh + Al*Bh
#pragma unroll
            for (int p = 0; p < 2; ++p)
                ldsm_x4(b[2*p][0], b[2*p][1], b[2*p+1][0], b[2*p+1][1],
                        aBh + p * (16 * ROWB) + kh * 32);
#pragma unroll
            for (int mt = 0; mt < 4; ++mt)
#pragma unroll
                for (int nt = 0; nt < 4; ++nt)
                    mma16816(acc[mt][nt], ah[mt], b[nt]);
#pragma unroll
            for (int mt = 0; mt < 4; ++mt)
#pragma unroll
                for (int nt = 0; nt < 4; ++nt)
                    mma16816(acc[mt][nt], al[mt], b[nt]);
            // Bl pass: Ah*Bl  (b regs reused)
#pragma unroll
            for (int p = 0; p < 2; ++p)
                ldsm_x4(b[2*p][0], b[2*p][1], b[2*p+1][0], b[2*p+1][1],
                        aBl + p * (16 * ROWB) + kh * 32);
#pragma unroll
            for (int mt = 0; mt < 4; ++mt)
#pragma unroll
                for (int nt = 0; nt < 4; ++nt)
                    mma16816(acc[mt][nt], ah[mt], b[nt]);
        }
        __syncthreads();
    }

    const int r0 = bm + wm * 64 + (lane >> 2);
    const int cc = bn + wn * 32 + (lane & 3) * 2;
    if (out_mode == 0) {
#pragma unroll
        for (int mt = 0; mt < 4; ++mt)
#pragma unroll
            for (int nt = 0; nt < 4; ++nt) {
                int rr = r0 + mt * 16;
                int cl = cc + nt * 8;
                *(float2*)&C[(size_t)rr * N + cl]       = make_float2(acc[mt][nt][0], acc[mt][nt][1]);
                *(float2*)&C[(size_t)(rr + 8) * N + cl] = make_float2(acc[mt][nt][2], acc[mt][nt][3]);
            }
    } else {
#pragma unroll
        for (int mt = 0; mt < 4; ++mt)
#pragma unroll
            for (int nt = 0; nt < 4; ++nt) {
#pragma unroll
                for (int half = 0; half < 2; ++half) {
                    int rr = r0 + mt * 16 + half * 8;
                    int cl = cc + nt * 8;
                    float y0 = acc[mt][nt][half * 2 + 0];
                    float y1 = acc[mt][nt][half * 2 + 1];
                    __nv_bfloat162 h, l;
                    h.x = __float2bfloat16(y0); h.y = __float2bfloat16(y1);
                    l.x = __float2bfloat16(y0 - __bfloat162float(h.x));
                    l.y = __float2bfloat16(y1 - __bfloat162float(h.y));
                    size_t o2 = ((size_t)rr * N + cl) >> 1;
                    ((__nv_bfloat162*)Ch)[o2] = h;
                    ((__nv_bfloat162*)Cl)[o2] = l;
                }
            }
    }
}

// ---------------- conv via split-bf16 mma -------------------------------------
__global__ __launch_bounds__(256, 2) void conv_mma(
        const __nv_bfloat16* __restrict__ Qh, const __nv_bfloat16* __restrict__ Ql,
        const __nv_bfloat16* __restrict__ Kh, const __nv_bfloat16* __restrict__ Kl,
        const __nv_bfloat16* __restrict__ WQh, const __nv_bfloat16* __restrict__ WQl,
        const __nv_bfloat16* __restrict__ WKh, const __nv_bfloat16* __restrict__ WKl,
        const float* __restrict__ bq, const float* __restrict__ bk,
        float* __restrict__ Yq, float* __restrict__ Yk) {
    extern __shared__ char smem[];
    uint32_t sb = smem_u32(smem);
    const int t = threadIdx.x, wid = t >> 5, lane = t & 31;
    const int wm = wid >> 2, wn = wid & 3;
    const int g  = blockIdx.x;
    const int bm = blockIdx.y * 128;
    const int cz = blockIdx.z;
    const __nv_bfloat16* Xh = cz ? Kh : Qh;
    const __nv_bfloat16* Xl = cz ? Kl : Ql;
    const __nv_bfloat16* Bh = cz ? WKh : WQh;
    const __nv_bfloat16* Bl = cz ? WKl : WQl;
    const float* bias = cz ? bk : bq;
    float* Y = cz ? Yk : Yq;

    float acc[4][4][4];
#pragma unroll
    for (int mt = 0; mt < 4; ++mt)
#pragma unroll
        for (int nt = 0; nt < 4; ++nt)
#pragma unroll
            for (int r = 0; r < 4; ++r) acc[mt][nt][r] = 0.f;

    const uint32_t rowA = wm * 64 + (lane & 15);
    const uint32_t colA = (uint32_t)(lane >> 4) << 4;
    const uint32_t rowB = wn * 32 + ((uint32_t)(lane >> 4) << 3) + (lane & 7);
    const uint32_t colB = (uint32_t)((lane >> 3) & 1) << 4;

    auto load_chunk = [&](uint32_t st, int k0) {
        int tap = k0 >> 7, i0 = k0 & 127;
#pragma unroll
        for (int i = 0; i < 8; ++i) {
            int idx = t + i * 256;
            int mat = idx >> 9;
            int j   = idx & 511;
            int row = j >> 2, c = j & 3;
            uint32_t dst = st + mat * MATB + row * ROWB + c * 16;
            if (mat < 2) {
                int s = bm + row - 3 + tap;
                const __nv_bfloat16* base = (mat == 0) ? Xh : Xl;
                if (s >= 0)
                    cp16(dst, base + (size_t)s * HID + g * 128 + i0 + c * 8);
                else
                    *(uint4*)(smem + (dst - sb)) = make_uint4(0, 0, 0, 0);
            } else {
                const __nv_bfloat16* base = (mat == 2) ? Bh : Bl;
                cp16(dst, base + (size_t)(g * 128 + row) * 512 + k0 + c * 8);
            }
        }
    };

    load_chunk(sb, 0);
    CP_COMMIT();
    for (int c = 0; c < 16; ++c) {
        uint32_t cur = (c & 1) ? STAGEB : 0u;
        if (c + 1 < 16) {
            load_chunk(sb + (cur ^ STAGEB), (c + 1) * 32);
            CP_COMMIT();
            CP_WAIT(1);
        } else {
            CP_WAIT(0);
        }
        __syncthreads();

        uint32_t aAh = sb + cur + rowA * ROWB + colA;
        uint32_t aAl = aAh + MATB;
        uint32_t aBh = sb + cur + 2 * MATB + rowB * ROWB + colB;
        uint32_t aBl = aBh + MATB;
#pragma unroll
        for (int kh = 0; kh < 2; ++kh) {
            uint32_t ah[4][4], al[4][4], b[4][2];
#pragma unroll
            for (int mt = 0; mt < 4; ++mt) {
                ldsm_x4(ah[mt][0], ah[mt][1], ah[mt][2], ah[mt][3],
                        aAh + mt * (16 * ROWB) + kh * 32);
                ldsm_x4(al[mt][0], al[mt][1], al[mt][2], al[mt][3],
                        aAl + mt * (16 * ROWB) + kh * 32);
            }
#pragma unroll
            for (int p = 0; p < 2; ++p)
                ldsm_x4(b[2*p][0], b[2*p][1], b[2*p+1][0], b[2*p+1][1],
                        aBh + p * (16 * ROWB) + kh * 32);
#pragma unroll
            for (int mt = 0; mt < 4; ++mt)
#pragma unroll
                for (int nt = 0; nt < 4; ++nt)
                    mma16816(acc[mt][nt], ah[mt], b[nt]);
#pragma unroll
            for (int mt = 0; mt < 4; ++mt)
#pragma unroll
                for (int nt = 0; nt < 4; ++nt)
                    mma16816(acc[mt][nt], al[mt], b[nt]);
#pragma unroll
            for (int p = 0; p < 2; ++p)
                ldsm_x4(b[2*p][0], b[2*p][1], b[2*p+1][0], b[2*p+1][1],
                        aBl + p * (16 * ROWB) + kh * 32);
#pragma unroll
            for (int mt = 0; mt < 4; ++mt)
#pragma unroll
                for (int nt = 0; nt < 4; ++nt)
                    mma16816(acc[mt][nt], ah[mt], b[nt]);
        }
        __syncthreads();
    }

    const int r0 = bm + wm * 64 + (lane >> 2);
    const int c0 = wn * 32 + (lane & 3) * 2;
#pragma unroll
    for (int mt = 0; mt < 4; ++mt)
#pragma unroll
        for (int nt = 0; nt < 4; ++nt) {
            int cl = c0 + nt * 8;
            float b0 = bias[g * 128 + cl], b1 = bias[g * 128 + cl + 1];
#pragma unroll
            for (int half = 0; half < 2; ++half) {
                int rr = r0 + mt * 16 + half * 8;
                float y0 = acc[mt][nt][half * 2 + 0] + b0;
                float y1 = acc[mt][nt][half * 2 + 1] + b1;
                y0 = y0 / (1.f + expf(-y0));
                y1 = y1 / (1.f + expf(-y1));
                *(float2*)&Y[(size_t)rr * HID + g * 128 + cl] = make_float2(y0, y1);
            }
        }
}

// ---------------- gate / beta -------------------------------------------------
__global__ __launch_bounds__(1024) void gates_kernel(const float* __restrict__ X,
        const float* __restrict__ Wg, const float* __restrict__ bg,
        const float* __restrict__ Wb, const float* __restrict__ bb,
        float* __restrict__ gate, float* __restrict__ beta) {
    __shared__ float xs[HID];
    const int s = blockIdx.x;
    for (int i = threadIdx.x; i < HID; i += 1024) xs[i] = X[(size_t)s * HID + i];
    __syncthreads();
    const int w = threadIdx.x >> 5, lane = threadIdx.x & 31;
    const float* row = (w < 16) ? (Wg + (size_t)w * HID) : (Wb + (size_t)(w - 16) * HID);
    float p = 0.f;
    for (int i = lane; i < HID; i += 32) p += xs[i] * row[i];
#pragma unroll
    for (int off = 16; off; off >>= 1) p += __shfl_xor_sync(0xffffffffu, p, off);
    if (lane == 0) {
        int hh = (w < 16) ? w : (w - 16);
        float bv = (w < 16) ? bg[hh] : bb[hh];
        float sv = 1.f / (1.f + expf(-(p + bv)));
        if (w < 16) gate[s * NHK + hh] = sv;
        else        beta[s * NHK + hh] = sv;
    }
}

// ---------------- sequential gated scan (split bf16 output) -------------------
__global__ __launch_bounds__(256) void scan_kernel(const float* __restrict__ Q,
        const float* __restrict__ K, const float* __restrict__ V,
        const float* __restrict__ Beta, const float* __restrict__ Gate,
        __nv_bfloat16* __restrict__ Oh, __nv_bfloat16* __restrict__ Ol,
        float* __restrict__ Sf) {
    __shared__ float qs[32][128];
    __shared__ float ks[32][128];
    __shared__ float vs[32][32];
    __shared__ float bs[32], gs[32];
    const int h  = blockIdx.x >> 3;
    const int c0 = (blockIdx.x & 7) * 32;
    const int t  = threadIdx.x;
    const int rg = t & 15;
    const int cg = t >> 4;

    float S0[8], S1[8];
#pragma unroll
    for (int a = 0; a < 8; ++a) { S0[a] = 0.f; S1[a] = 0.f; }

    for (int s0 = 0; s0 < SQ; s0 += 32) {
        for (int idx = t; idx < 32 * 128; idx += 256) {
            int tt = idx >> 7, col = idx & 127;
            qs[tt][col] = Q[(size_t)(s0 + tt) * HID + h * 128 + col];
            ks[tt][col] = K[(size_t)(s0 + tt) * HID + h * 128 + col];
        }
        for (int idx = t; idx < 32 * 32; idx += 256) {
            int tt = idx >> 5, col = idx & 31;
            vs[tt][col] = V[(size_t)(s0 + tt) * NVD + h * 256 + c0 + col];
        }
        if (t < 32) {
            bs[t] = Beta[(s0 + t) * NHK + h];
            gs[t] = Gate[(s0 + t) * NHK + h];
        }
        __syncthreads();
        for (int tt = 0; tt < 32; ++tt) {
            float bt = bs[tt];
            float v0 = vs[tt][cg * 2 + 0];
            float v1 = vs[tt][cg * 2 + 1];
            float p0 = 0.f, p1 = 0.f;
#pragma unroll
            for (int a = 0; a < 8; ++a) {
                float kr = ks[tt][rg + 16 * a];
                float qr = qs[tt][rg + 16 * a];
                S0[a] = bt * S0[a] + kr * v0;
                S1[a] = bt * S1[a] + kr * v1;
                p0 += qr * S0[a];
                p1 += qr * S1[a];
            }
#pragma unroll
            for (int off = 8; off; off >>= 1) {
                p0 += __shfl_xor_sync(0xffffffffu, p0, off);
                p1 += __shfl_xor_sync(0xffffffffu, p1, off);
            }
            if (rg == 0) {
                float gt = gs[tt];
                float y0 = gt * p0, y1 = gt * p1;
                __nv_bfloat162 hv, lv;
                hv.x = __float2bfloat16(y0); hv.y = __float2bfloat16(y1);
                lv.x = __float2bfloat16(y0 - __bfloat162float(hv.x));
                lv.y = __float2bfloat16(y1 - __bfloat162float(hv.y));
                size_t o2 = ((size_t)(s0 + tt) * NVD + h * 256 + c0 + cg * 2) >> 1;
                ((__nv_bfloat162*)Oh)[o2] = hv;
                ((__nv_bfloat162*)Ol)[o2] = lv;
            }
        }
        __syncthreads();
    }
    if (Sf != nullptr) {
#pragma unroll
        for (int a = 0; a < 8; ++a) {
            size_t base = (size_t)h * KDIM * VDIM + (size_t)(rg + 16 * a) * VDIM
                        + c0 + cg * 2;
            Sf[base]     = S0[a];
            Sf[base + 1] = S1[a];
        }
    }
}

// ---------------- launch ------------------------------------------------------
extern "C" void kernel_launch(void* const* d_in, const int* in_sizes, int n_in,
                              void* d_out, int out_size) {
    const float* x   = (const float*)d_in[0];
    const float* Wq  = (const float*)d_in[1];
    const float* Wk  = (const float*)d_in[2];
    const float* Wv  = (const float*)d_in[3];
    const float* Wo  = (const float*)d_in[4];
    const float* Wqc = (const float*)d_in[5];
    const float* bqc = (const float*)d_in[6];
    const float* Wkc = (const float*)d_in[7];
    const float* bkc = (const float*)d_in[8];
    const float* Wg  = (const float*)d_in[9];
    const float* bg  = (const float*)d_in[10];
    const float* Wb  = (const float*)d_in[11];
    const float* bb  = (const float*)d_in[12];
    float* out = (float*)d_out;

    float *dv, *dqc, *dkc, *dgate, *dbeta;
    cudaGetSymbolAddress((void**)&dv,    g_v);
    cudaGetSymbolAddress((void**)&dqc,   g_qc);
    cudaGetSymbolAddress((void**)&dkc,   g_kc);
    cudaGetSymbolAddress((void**)&dgate, g_gate);
    cudaGetSymbolAddress((void**)&dbeta, g_beta);

    __nv_bfloat16 *xh, *xl, *wqh, *wql, *wkh, *wkl, *wvh, *wvl, *woh, *wol, *ah, *al;
    __nv_bfloat16 *qph, *qpl, *kph, *kpl, *cqh, *cql, *ckh, *ckl;
    cudaGetSymbolAddress((void**)&xh,  g_xh);  cudaGetSymbolAddress((void**)&xl,  g_xl);
    cudaGetSymbolAddress((void**)&wqh, g_wqh); cudaGetSymbolAddress((void**)&wql, g_wql);
    cudaGetSymbolAddress((void**)&wkh, g_wkh); cudaGetSymbolAddress((void**)&wkl, g_wkl);
    cudaGetSymbolAddress((void**)&wvh, g_wvh); cudaGetSymbolAddress((void**)&wvl, g_wvl);
    cudaGetSymbolAddress((void**)&woh, g_woh); cudaGetSymbolAddress((void**)&wol, g_wol);
    cudaGetSymbolAddress((void**)&ah,  g_ah);  cudaGetSymbolAddress((void**)&al,  g_al);
    cudaGetSymbolAddress((void**)&qph, g_qph); cudaGetSymbolAddress((void**)&qpl, g_qpl);
    cudaGetSymbolAddress((void**)&kph, g_kph); cudaGetSymbolAddress((void**)&kpl, g_kpl);
    cudaGetSymbolAddress((void**)&cqh, g_cqh); cudaGetSymbolAddress((void**)&cql, g_cql);
    cudaGetSymbolAddress((void**)&ckh, g_ckh); cudaGetSymbolAddress((void**)&ckl, g_ckl);

    cudaFuncSetAttribute(gemm_mma, cudaFuncAttributeMaxDynamicSharedMemorySize, GSMEM);
    cudaFuncSetAttribute(conv_mma, cudaFuncAttributeMaxDynamicSharedMemorySize, GSMEM);

    dim3 blk(256);
    // 0: input splits
    split_all<<<57344, blk>>>(
        (const float2*)x,  (__nv_bfloat162*)xh,  (__nv_bfloat162*)xl,
        (const float2*)Wq, (__nv_bfloat162*)wqh, (__nv_bfloat162*)wql,
        (const float2*)Wk, (__nv_bfloat162*)wkh, (__nv_bfloat162*)wkl,
        (const float2*)Wv, (__nv_bfloat162*)wvh, (__nv_bfloat162*)wvl,
        (const float2*)Wo, (__nv_bfloat162*)woh, (__nv_bfloat162*)wol);
    // 1: conv weight reshape + split
    convw_reshape<<<8192, blk>>>(Wqc, cqh, cql, Wkc, ckh, ckl);
    // 2: gates
    gates_kernel<<<SQ, 1024>>>(x, Wg, bg, Wb, bb, dgate, dbeta);
    // 3,4: q/k projections with fused split output
    gemm_mma<<<dim3(HID/128, SQ/128), blk, GSMEM>>>(xh, xl, wqh, wql,
        nullptr, qph, qpl, SQ, HID, HID, 1);
    gemm_mma<<<dim3(HID/128, SQ/128), blk, GSMEM>>>(xh, xl, wkh, wkl,
        nullptr, kph, kpl, SQ, HID, HID, 1);
    // 5: v projection fp32 (profiled by ncu -s 5 -c 1)
    gemm_mma<<<dim3(NVD/128, SQ/128), blk, GSMEM>>>(xh, xl, wvh, wvl,
        dv, nullptr, nullptr, SQ, NVD, HID, 0);
    // 6: both convs on tensor cores
    conv_mma<<<dim3(16, 16, 2), blk, GSMEM>>>(qph, qpl, kph, kpl,
                                              cqh, cql, ckh, ckl,
                                              bqc, bkc, dqc, dkc);
    // 7: recurrent scan with fused split output
    float* Sf = (out_size >= OUT_ELEMS + SF_ELEMS) ? (out + OUT_ELEMS) : nullptr;
    scan_kernel<<<128, blk>>>(dqc, dkc, dv, dbeta, dgate, ah, al, Sf);
    // 8: output projection
    gemm_mma<<<dim3(HID/128, SQ/128), blk, GSMEM>>>(ah, al, woh, wol,
        out, nullptr, nullptr, SQ, HID, NVD, 0);
}

// round 7
// speedup vs baseline: 2.0062x; 1.0198x over previous
#include <cuda_runtime.h>
#include <cuda_bf16.h>
#include <math.h>
#include <cstdint>

#define SQ   2048
#define HID  2048
#define NHK  16
#define KDIM 128
#define VDIM 256
#define NVD  4096
#define OUT_ELEMS  (SQ*HID)
#define SF_ELEMS   (NHK*KDIM*VDIM)

// ---------------- scratch -----------------------------------------------------
__device__ __align__(256) float g_v   [SQ*NVD];
__device__ __align__(256) float g_qc  [SQ*HID];
__device__ __align__(256) float g_kc  [SQ*HID];
__device__ __align__(256) float g_gate[SQ*NHK];
__device__ __align__(256) float g_beta[SQ*NHK];

__device__ __align__(256) __nv_bfloat16 g_xh [SQ*HID],  g_xl [SQ*HID];
__device__ __align__(256) __nv_bfloat16 g_wqh[HID*HID], g_wql[HID*HID];
__device__ __align__(256) __nv_bfloat16 g_wkh[HID*HID], g_wkl[HID*HID];
__device__ __align__(256) __nv_bfloat16 g_wvh[NVD*HID], g_wvl[NVD*HID];
__device__ __align__(256) __nv_bfloat16 g_woh[HID*NVD], g_wol[HID*NVD];
__device__ __align__(256) __nv_bfloat16 g_ah [SQ*NVD],  g_al [SQ*NVD];
__device__ __align__(256) __nv_bfloat16 g_qph[SQ*HID],  g_qpl[SQ*HID];
__device__ __align__(256) __nv_bfloat16 g_kph[SQ*HID],  g_kpl[SQ*HID];
__device__ __align__(256) __nv_bfloat16 g_cqh[HID*512], g_cql[HID*512];
__device__ __align__(256) __nv_bfloat16 g_ckh[HID*512], g_ckl[HID*512];

// ---------------- PTX helpers --------------------------------------------------
__device__ __forceinline__ uint32_t smem_u32(const void* p) {
    uint32_t a;
    asm("{ .reg .u64 t; cvta.to.shared.u64 t, %1; cvt.u32.u64 %0, t; }" : "=r"(a) : "l"(p));
    return a;
}
__device__ __forceinline__ void cp16(uint32_t dst, const void* src) {
    asm volatile("cp.async.cg.shared.global [%0], [%1], 16;" :: "r"(dst), "l"(src));
}
#define CP_COMMIT() asm volatile("cp.async.commit_group;")
#define CP_WAIT(n)  asm volatile("cp.async.wait_group %0;" :: "n"(n))

__device__ __forceinline__ void ldsm_x4(uint32_t& r0, uint32_t& r1, uint32_t& r2,
                                        uint32_t& r3, uint32_t a) {
    asm volatile("ldmatrix.sync.aligned.m8n8.x4.shared.b16 {%0,%1,%2,%3}, [%4];"
                 : "=r"(r0), "=r"(r1), "=r"(r2), "=r"(r3) : "r"(a));
}
__device__ __forceinline__ void mma16816(float* d, const uint32_t* a, const uint32_t* b) {
    asm volatile(
        "mma.sync.aligned.m16n8k16.row.col.f32.bf16.bf16.f32 "
        "{%0,%1,%2,%3},{%4,%5,%6,%7},{%8,%9},{%0,%1,%2,%3};"
        : "+f"(d[0]), "+f"(d[1]), "+f"(d[2]), "+f"(d[3])
        : "r"(a[0]), "r"(a[1]), "r"(a[2]), "r"(a[3]), "r"(b[0]), "r"(b[1]));
}

// ---------------- split kernels -----------------------------------------------
__device__ __forceinline__ void split_one(const float2* X, __nv_bfloat162* H,
                                          __nv_bfloat162* L, int i) {
    float2 x = X[i];
    __nv_bfloat16 hx = __float2bfloat16(x.x), hy = __float2bfloat16(x.y);
    float rx = x.x - __bfloat162float(hx);
    float ry = x.y - __bfloat162float(hy);
    __nv_bfloat162 h; h.x = hx; h.y = hy;
    __nv_bfloat162 l; l.x = __float2bfloat16(rx); l.y = __float2bfloat16(ry);
    H[i] = h; L[i] = l;
}

__global__ __launch_bounds__(256) void split_all(
        const float2* x,  __nv_bfloat162* xh,  __nv_bfloat162* xl,
        const float2* wq, __nv_bfloat162* wqh, __nv_bfloat162* wql,
        const float2* wk, __nv_bfloat162* wkh, __nv_bfloat162* wkl,
        const float2* wv, __nv_bfloat162* wvh, __nv_bfloat162* wvl,
        const float2* wo, __nv_bfloat162* woh, __nv_bfloat162* wol) {
    int b = blockIdx.x;
    if (b < 8192)       split_one(x,  xh,  xl,  (b)         * 256 + threadIdx.x);
    else if (b < 16384) split_one(wq, wqh, wql, (b - 8192)  * 256 + threadIdx.x);
    else if (b < 24576) split_one(wk, wkh, wkl, (b - 16384) * 256 + threadIdx.x);
    else if (b < 40960) split_one(wv, wvh, wvl, (b - 24576) * 256 + threadIdx.x);
    else                split_one(wo, woh, wol, (b - 40960) * 256 + threadIdx.x);
}

__global__ __launch_bounds__(256) void convw_reshape(
        const float* __restrict__ Wq, __nv_bfloat16* __restrict__ Qh, __nv_bfloat16* __restrict__ Ql,
        const float* __restrict__ Wk, __nv_bfloat16* __restrict__ Kh, __nv_bfloat16* __restrict__ Kl) {
    int b = blockIdx.x;
    const float* W = (b < 4096) ? Wq : Wk;
    __nv_bfloat16* H = (b < 4096) ? Qh : Kh;
    __nv_bfloat16* L = (b < 4096) ? Ql : Kl;
    int e = ((b < 4096) ? b : (b - 4096)) * 256 + threadIdx.x;
    int o = e >> 9, kk = e & 511;
    int tap = kk >> 7, i = kk & 127;
    float v = W[o * 512 + i * 4 + tap];
    __nv_bfloat16 h = __float2bfloat16(v);
    H[e] = h;
    L[e] = __float2bfloat16(v - __bfloat162float(h));
}

// ---------------- common GEMM pieces ------------------------------------------
#define ROWB  80u
#define MATB  (128u*ROWB)
#define STAGEB (4u*MATB)
#define GSMEM  (2u*STAGEB)

__device__ __forceinline__ void ld_stage(uint32_t st,
        const __nv_bfloat16* __restrict__ Ah, const __nv_bfloat16* __restrict__ Al,
        const __nv_bfloat16* __restrict__ Bh, const __nv_bfloat16* __restrict__ Bl,
        int bm, int bn, int k0, int K, int t) {
#pragma unroll
    for (int i = 0; i < 8; ++i) {
        int idx = t + i * 256;
        int mat = idx >> 9;
        int j   = idx & 511;
        int row = j >> 2, c = j & 3;
        const __nv_bfloat16* base = (mat == 0) ? Ah : (mat == 1) ? Al
                                   : (mat == 2) ? Bh : Bl;
        int grow = ((mat < 2) ? bm : bn) + row;
        cp16(st + mat * MATB + row * ROWB + c * 16,
             base + (size_t)grow * K + k0 + c * 8);
    }
}

// compute one K=32 chunk from stage at 'cur' into acc
__device__ __forceinline__ void chunk_compute(uint32_t sb, uint32_t cur,
        uint32_t rowA, uint32_t colA, uint32_t rowB, uint32_t colB,
        float acc[4][4][4]) {
    uint32_t aAh = sb + cur + rowA * ROWB + colA;
    uint32_t aAl = aAh + MATB;
    uint32_t aBh = sb + cur + 2 * MATB + rowB * ROWB + colB;
    uint32_t aBl = aBh + MATB;
#pragma unroll
    for (int kh = 0; kh < 2; ++kh) {
        uint32_t ah[4][4], al[4][4], b[4][2];
#pragma unroll
        for (int mt = 0; mt < 4; ++mt) {
            ldsm_x4(ah[mt][0], ah[mt][1], ah[mt][2], ah[mt][3],
                    aAh + mt * (16 * ROWB) + kh * 32);
            ldsm_x4(al[mt][0], al[mt][1], al[mt][2], al[mt][3],
                    aAl + mt * (16 * ROWB) + kh * 32);
        }
#pragma unroll
        for (int p = 0; p < 2; ++p)
            ldsm_x4(b[2*p][0], b[2*p][1], b[2*p+1][0], b[2*p+1][1],
                    aBh + p * (16 * ROWB) + kh * 32);
#pragma unroll
        for (int mt = 0; mt < 4; ++mt)
#pragma unroll
            for (int nt = 0; nt < 4; ++nt)
                mma16816(acc[mt][nt], ah[mt], b[nt]);
#pragma unroll
        for (int mt = 0; mt < 4; ++mt)
#pragma unroll
            for (int nt = 0; nt < 4; ++nt)
                mma16816(acc[mt][nt], al[mt], b[nt]);
#pragma unroll
        for (int p = 0; p < 2; ++p)
            ldsm_x4(b[2*p][0], b[2*p][1], b[2*p+1][0], b[2*p+1][1],
                    aBl + p * (16 * ROWB) + kh * 32);
#pragma unroll
        for (int mt = 0; mt < 4; ++mt)
#pragma unroll
            for (int nt = 0; nt < 4; ++nt)
                mma16816(acc[mt][nt], ah[mt], b[nt]);
    }
}

// ---------------- fused q/k/v projection --------------------------------------
// blocks 0..255: q tiles (split out), 256..511: k tiles (split out),
// 512..1023: v tiles (fp32 out, N=4096). K=2048 for all, A = xh/xl.
__global__ __launch_bounds__(256, 2) void proj_fused(
        const __nv_bfloat16* __restrict__ Xh, const __nv_bfloat16* __restrict__ Xl,
        const __nv_bfloat16* __restrict__ WQh, const __nv_bfloat16* __restrict__ WQl,
        const __nv_bfloat16* __restrict__ WKh, const __nv_bfloat16* __restrict__ WKl,
        const __nv_bfloat16* __restrict__ WVh, const __nv_bfloat16* __restrict__ WVl,
        __nv_bfloat16* __restrict__ Qh, __nv_bfloat16* __restrict__ Ql,
        __nv_bfloat16* __restrict__ Kh, __nv_bfloat16* __restrict__ Kl,
        float* __restrict__ V) {
    extern __shared__ char smem[];
    uint32_t sb = smem_u32(smem);
    const int t = threadIdx.x, wid = t >> 5, lane = t & 31;
    const int wm = wid >> 2, wn = wid & 3;

    int bx = blockIdx.x;
    int which, bm, bn;
    const __nv_bfloat16 *Bh_, *Bl_;
    if (bx < 256)      { which = 0; bm = (bx >> 4) << 7;          bn = (bx & 15) << 7; Bh_ = WQh; Bl_ = WQl; }
    else if (bx < 512) { which = 1; int i = bx - 256; bm = (i >> 4) << 7; bn = (i & 15) << 7; Bh_ = WKh; Bl_ = WKl; }
    else               { which = 2; int i = bx - 512; bm = (i >> 5) << 7; bn = (i & 31) << 7; Bh_ = WVh; Bl_ = WVl; }

    float acc[4][4][4];
#pragma unroll
    for (int mt = 0; mt < 4; ++mt)
#pragma unroll
        for (int nt = 0; nt < 4; ++nt)
#pragma unroll
            for (int r = 0; r < 4; ++r) acc[mt][nt][r] = 0.f;

    const uint32_t rowA = wm * 64 + (lane & 15);
    const uint32_t colA = (uint32_t)(lane >> 4) << 4;
    const uint32_t rowB = wn * 32 + ((uint32_t)(lane >> 4) << 3) + (lane & 7);
    const uint32_t colB = (uint32_t)((lane >> 3) & 1) << 4;

    const int nch = HID / 32;   // 64
    ld_stage(sb, Xh, Xl, Bh_, Bl_, bm, bn, 0, HID, t);
    CP_COMMIT();
    for (int c = 0; c < nch; ++c) {
        uint32_t cur = (c & 1) ? STAGEB : 0u;
        CP_WAIT(0);
        __syncthreads();
        if (c + 1 < nch) {
            ld_stage(sb + (cur ^ STAGEB), Xh, Xl, Bh_, Bl_, bm, bn, (c + 1) * 32, HID, t);
            CP_COMMIT();
        }
        chunk_compute(sb, cur, rowA, colA, rowB, colB, acc);
    }

    const int r0 = bm + wm * 64 + (lane >> 2);
    const int ccl = wn * 32 + (lane & 3) * 2;   // col within tile
    if (which < 2) {
        __nv_bfloat16* Ch = which ? Kh : Qh;
        __nv_bfloat16* Cl = which ? Kl : Ql;
#pragma unroll
        for (int mt = 0; mt < 4; ++mt)
#pragma unroll
            for (int nt = 0; nt < 4; ++nt)
#pragma unroll
                for (int half = 0; half < 2; ++half) {
                    int rr = r0 + mt * 16 + half * 8;
                    int cl = bn + ccl + nt * 8;
                    float y0 = acc[mt][nt][half * 2 + 0];
                    float y1 = acc[mt][nt][half * 2 + 1];
                    __nv_bfloat162 h, l;
                    h.x = __float2bfloat16(y0); h.y = __float2bfloat16(y1);
                    l.x = __float2bfloat16(y0 - __bfloat162float(h.x));
                    l.y = __float2bfloat16(y1 - __bfloat162float(h.y));
                    size_t o2 = ((size_t)rr * HID + cl) >> 1;
                    ((__nv_bfloat162*)Ch)[o2] = h;
                    ((__nv_bfloat162*)Cl)[o2] = l;
                }
    } else {
#pragma unroll
        for (int mt = 0; mt < 4; ++mt)
#pragma unroll
            for (int nt = 0; nt < 4; ++nt) {
                int rr = r0 + mt * 16;
                int cl = bn + ccl + nt * 8;
                *(float2*)&V[(size_t)rr * NVD + cl]       = make_float2(acc[mt][nt][0], acc[mt][nt][1]);
                *(float2*)&V[(size_t)(rr + 8) * NVD + cl] = make_float2(acc[mt][nt][2], acc[mt][nt][3]);
            }
    }
}

// ---------------- output projection: C = A * B^T, fp32 out --------------------
__global__ __launch_bounds__(256, 2) void gemm_mma(
        const __nv_bfloat16* __restrict__ Ah, const __nv_bfloat16* __restrict__ Al,
        const __nv_bfloat16* __restrict__ Bh, const __nv_bfloat16* __restrict__ Bl,
        float* __restrict__ C, int M, int N, int K) {
    extern __shared__ char smem[];
    uint32_t sb = smem_u32(smem);
    const int t = threadIdx.x, wid = t >> 5, lane = t & 31;
    const int wm = wid >> 2, wn = wid & 3;
    const int bm = blockIdx.y * 128, bn = blockIdx.x * 128;

    float acc[4][4][4];
#pragma unroll
    for (int mt = 0; mt < 4; ++mt)
#pragma unroll
        for (int nt = 0; nt < 4; ++nt)
#pragma unroll
            for (int r = 0; r < 4; ++r) acc[mt][nt][r] = 0.f;

    const uint32_t rowA = wm * 64 + (lane & 15);
    const uint32_t colA = (uint32_t)(lane >> 4) << 4;
    const uint32_t rowB = wn * 32 + ((uint32_t)(lane >> 4) << 3) + (lane & 7);
    const uint32_t colB = (uint32_t)((lane >> 3) & 1) << 4;

    const int nch = K / 32;
    ld_stage(sb, Ah, Al, Bh, Bl, bm, bn, 0, K, t);
    CP_COMMIT();
    for (int c = 0; c < nch; ++c) {
        uint32_t cur = (c & 1) ? STAGEB : 0u;
        CP_WAIT(0);
        __syncthreads();
        if (c + 1 < nch) {
            ld_stage(sb + (cur ^ STAGEB), Ah, Al, Bh, Bl, bm, bn, (c + 1) * 32, K, t);
            CP_COMMIT();
        }
        chunk_compute(sb, cur, rowA, colA, rowB, colB, acc);
    }

    const int r0 = bm + wm * 64 + (lane >> 2);
    const int cc = bn + wn * 32 + (lane & 3) * 2;
#pragma unroll
    for (int mt = 0; mt < 4; ++mt)
#pragma unroll
        for (int nt = 0; nt < 4; ++nt) {
            int rr = r0 + mt * 16;
            int cl = cc + nt * 8;
            *(float2*)&C[(size_t)rr * N + cl]       = make_float2(acc[mt][nt][0], acc[mt][nt][1]);
            *(float2*)&C[(size_t)(rr + 8) * N + cl] = make_float2(acc[mt][nt][2], acc[mt][nt][3]);
        }
}

// ---------------- conv via split-bf16 mma -------------------------------------
__global__ __launch_bounds__(256, 2) void conv_mma(
        const __nv_bfloat16* __restrict__ Qh, const __nv_bfloat16* __restrict__ Ql,
        const __nv_bfloat16* __restrict__ Kh, const __nv_bfloat16* __restrict__ Kl,
        const __nv_bfloat16* __restrict__ WQh, const __nv_bfloat16* __restrict__ WQl,
        const __nv_bfloat16* __restrict__ WKh, const __nv_bfloat16* __restrict__ WKl,
        const float* __restrict__ bq, const float* __restrict__ bk,
        float* __restrict__ Yq, float* __restrict__ Yk) {
    extern __shared__ char smem[];
    uint32_t sb = smem_u32(smem);
    const int t = threadIdx.x, wid = t >> 5, lane = t & 31;
    const int wm = wid >> 2, wn = wid & 3;
    const int g  = blockIdx.x;
    const int bm = blockIdx.y * 128;
    const int cz = blockIdx.z;
    const __nv_bfloat16* Xh = cz ? Kh : Qh;
    const __nv_bfloat16* Xl = cz ? Kl : Ql;
    const __nv_bfloat16* Bh = cz ? WKh : WQh;
    const __nv_bfloat16* Bl = cz ? WKl : WQl;
    const float* bias = cz ? bk : bq;
    float* Y = cz ? Yk : Yq;

    float acc[4][4][4];
#pragma unroll
    for (int mt = 0; mt < 4; ++mt)
#pragma unroll
        for (int nt = 0; nt < 4; ++nt)
#pragma unroll
            for (int r = 0; r < 4; ++r) acc[mt][nt][r] = 0.f;

    const uint32_t rowA = wm * 64 + (lane & 15);
    const uint32_t colA = (uint32_t)(lane >> 4) << 4;
    const uint32_t rowB = wn * 32 + ((uint32_t)(lane >> 4) << 3) + (lane & 7);
    const uint32_t colB = (uint32_t)((lane >> 3) & 1) << 4;

    auto load_chunk = [&](uint32_t st, int k0) {
        int tap = k0 >> 7, i0 = k0 & 127;
#pragma unroll
        for (int i = 0; i < 8; ++i) {
            int idx = t + i * 256;
            int mat = idx >> 9;
            int j   = idx & 511;
            int row = j >> 2, c = j & 3;
            uint32_t dst = st + mat * MATB + row * ROWB + c * 16;
            if (mat < 2) {
                int s = bm + row - 3 + tap;
                const __nv_bfloat16* base = (mat == 0) ? Xh : Xl;
                if (s >= 0)
                    cp16(dst, base + (size_t)s * HID + g * 128 + i0 + c * 8);
                else
                    *(uint4*)(smem + (dst - sb)) = make_uint4(0, 0, 0, 0);
            } else {
                const __nv_bfloat16* base = (mat == 2) ? Bh : Bl;
                cp16(dst, base + (size_t)(g * 128 + row) * 512 + k0 + c * 8);
            }
        }
    };

    load_chunk(sb, 0);
    CP_COMMIT();
    for (int c = 0; c < 16; ++c) {
        uint32_t cur = (c & 1) ? STAGEB : 0u;
        CP_WAIT(0);
        __syncthreads();
        if (c + 1 < 16) {
            load_chunk(sb + (cur ^ STAGEB), (c + 1) * 32);
            CP_COMMIT();
        }
        chunk_compute(sb, cur, rowA, colA, rowB, colB, acc);
    }

    const int r0 = bm + wm * 64 + (lane >> 2);
    const int c0 = wn * 32 + (lane & 3) * 2;
#pragma unroll
    for (int mt = 0; mt < 4; ++mt)
#pragma unroll
        for (int nt = 0; nt < 4; ++nt) {
            int cl = c0 + nt * 8;
            float b0 = bias[g * 128 + cl], b1 = bias[g * 128 + cl + 1];
#pragma unroll
            for (int half = 0; half < 2; ++half) {
                int rr = r0 + mt * 16 + half * 8;
                float y0 = acc[mt][nt][half * 2 + 0] + b0;
                float y1 = acc[mt][nt][half * 2 + 1] + b1;
                y0 = y0 / (1.f + expf(-y0));
                y1 = y1 / (1.f + expf(-y1));
                *(float2*)&Y[(size_t)rr * HID + g * 128 + cl] = make_float2(y0, y1);
            }
        }
}

// ---------------- gate / beta -------------------------------------------------
__global__ __launch_bounds__(1024) void gates_kernel(const float* __restrict__ X,
        const float* __restrict__ Wg, const float* __restrict__ bg,
        const float* __restrict__ Wb, const float* __restrict__ bb,
        float* __restrict__ gate, float* __restrict__ beta) {
    __shared__ float xs[HID];
    const int s = blockIdx.x;
    for (int i = threadIdx.x; i < HID; i += 1024) xs[i] = X[(size_t)s * HID + i];
    __syncthreads();
    const int w = threadIdx.x >> 5, lane = threadIdx.x & 31;
    const float* row = (w < 16) ? (Wg + (size_t)w * HID) : (Wb + (size_t)(w - 16) * HID);
    float p = 0.f;
    for (int i = lane; i < HID; i += 32) p += xs[i] * row[i];
#pragma unroll
    for (int off = 16; off; off >>= 1) p += __shfl_xor_sync(0xffffffffu, p, off);
    if (lane == 0) {
        int hh = (w < 16) ? w : (w - 16);
        float bv = (w < 16) ? bg[hh] : bb[hh];
        float sv = 1.f / (1.f + expf(-(p + bv)));
        if (w < 16) gate[s * NHK + hh] = sv;
        else        beta[s * NHK + hh] = sv;
    }
}

// ---------------- sequential gated scan (split bf16 output) -------------------
__global__ __launch_bounds__(256) void scan_kernel(const float* __restrict__ Q,
        const float* __restrict__ K, const float* __restrict__ V,
        const float* __restrict__ Beta, const float* __restrict__ Gate,
        __nv_bfloat16* __restrict__ Oh, __nv_bfloat16* __restrict__ Ol,
        float* __restrict__ Sf) {
    __shared__ float qs[32][128];
    __shared__ float ks[32][128];
    __shared__ float vs[32][32];
    __shared__ float bs[32], gs[32];
    const int h  = blockIdx.x >> 3;
    const int c0 = (blockIdx.x & 7) * 32;
    const int t  = threadIdx.x;
    const int rg = t & 15;
    const int cg = t >> 4;

    float S0[8], S1[8];
#pragma unroll
    for (int a = 0; a < 8; ++a) { S0[a] = 0.f; S1[a] = 0.f; }

    for (int s0 = 0; s0 < SQ; s0 += 32) {
        for (int idx = t; idx < 32 * 128; idx += 256) {
            int tt = idx >> 7, col = idx & 127;
            qs[tt][col] = Q[(size_t)(s0 + tt) * HID + h * 128 + col];
            ks[tt][col] = K[(size_t)(s0 + tt) * HID + h * 128 + col];
        }
        for (int idx = t; idx < 32 * 32; idx += 256) {
            int tt = idx >> 5, col = idx & 31;
            vs[tt][col] = V[(size_t)(s0 + tt) * NVD + h * 256 + c0 + col];
        }
        if (t < 32) {
            bs[t] = Beta[(s0 + t) * NHK + h];
            gs[t] = Gate[(s0 + t) * NHK + h];
        }
        __syncthreads();
        for (int tt = 0; tt < 32; ++tt) {
            float bt = bs[tt];
            float v0 = vs[tt][cg * 2 + 0];
            float v1 = vs[tt][cg * 2 + 1];
            float p0 = 0.f, p1 = 0.f;
#pragma unroll
            for (int a = 0; a < 8; ++a) {
                float kr = ks[tt][rg + 16 * a];
                float qr = qs[tt][rg + 16 * a];
                S0[a] = bt * S0[a] + kr * v0;
                S1[a] = bt * S1[a] + kr * v1;
                p0 += qr * S0[a];
                p1 += qr * S1[a];
            }
#pragma unroll
            for (int off = 8; off; off >>= 1) {
                p0 += __shfl_xor_sync(0xffffffffu, p0, off);
                p1 += __shfl_xor_sync(0xffffffffu, p1, off);
            }
            if (rg == 0) {
                float gt = gs[tt];
                float y0 = gt * p0, y1 = gt * p1;
                __nv_bfloat162 hv, lv;
                hv.x = __float2bfloat16(y0); hv.y = __float2bfloat16(y1);
                lv.x = __float2bfloat16(y0 - __bfloat162float(hv.x));
                lv.y = __float2bfloat16(y1 - __bfloat162float(hv.y));
                size_t o2 = ((size_t)(s0 + tt) * NVD + h * 256 + c0 + cg * 2) >> 1;
                ((__nv_bfloat162*)Oh)[o2] = hv;
                ((__nv_bfloat162*)Ol)[o2] = lv;
            }
        }
        __syncthreads();
    }
    if (Sf != nullptr) {
#pragma unroll
        for (int a = 0; a < 8; ++a) {
            size_t base = (size_t)h * KDIM * VDIM + (size_t)(rg + 16 * a) * VDIM
                        + c0 + cg * 2;
            Sf[base]     = S0[a];
            Sf[base + 1] = S1[a];
        }
    }
}

// ---------------- launch ------------------------------------------------------
extern "C" void kernel_launch(void* const* d_in, const int* in_sizes, int n_in,
                              void* d_out, int out_size) {
    const float* x   = (const float*)d_in[0];
    const float* Wq  = (const float*)d_in[1];
    const float* Wk  = (const float*)d_in[2];
    const float* Wv  = (const float*)d_in[3];
    const float* Wo  = (const float*)d_in[4];
    const float* Wqc = (const float*)d_in[5];
    const float* bqc = (const float*)d_in[6];
    const float* Wkc = (const float*)d_in[7];
    const float* bkc = (const float*)d_in[8];
    const float* Wg  = (const float*)d_in[9];
    const float* bg  = (const float*)d_in[10];
    const float* Wb  = (const float*)d_in[11];
    const float* bb  = (const float*)d_in[12];
    float* out = (float*)d_out;

    float *dv, *dqc, *dkc, *dgate, *dbeta;
    cudaGetSymbolAddress((void**)&dv,    g_v);
    cudaGetSymbolAddress((void**)&dqc,   g_qc);
    cudaGetSymbolAddress((void**)&dkc,   g_kc);
    cudaGetSymbolAddress((void**)&dgate, g_gate);
    cudaGetSymbolAddress((void**)&dbeta, g_beta);

    __nv_bfloat16 *xh, *xl, *wqh, *wql, *wkh, *wkl, *wvh, *wvl, *woh, *wol, *ah, *al;
    __nv_bfloat16 *qph, *qpl, *kph, *kpl, *cqh, *cql, *ckh, *ckl;
    cudaGetSymbolAddress((void**)&xh,  g_xh);  cudaGetSymbolAddress((void**)&xl,  g_xl);
    cudaGetSymbolAddress((void**)&wqh, g_wqh); cudaGetSymbolAddress((void**)&wql, g_wql);
    cudaGetSymbolAddress((void**)&wkh, g_wkh); cudaGetSymbolAddress((void**)&wkl, g_wkl);
    cudaGetSymbolAddress((void**)&wvh, g_wvh); cudaGetSymbolAddress((void**)&wvl, g_wvl);
    cudaGetSymbolAddress((void**)&woh, g_woh); cudaGetSymbolAddress((void**)&wol, g_wol);
    cudaGetSymbolAddress((void**)&ah,  g_ah);  cudaGetSymbolAddress((void**)&al,  g_al);
    cudaGetSymbolAddress((void**)&qph, g_qph); cudaGetSymbolAddress((void**)&qpl, g_qpl);
    cudaGetSymbolAddress((void**)&kph, g_kph); cudaGetSymbolAddress((void**)&kpl, g_kpl);
    cudaGetSymbolAddress((void**)&cqh, g_cqh); cudaGetSymbolAddress((void**)&cql, g_cql);
    cudaGetSymbolAddress((void**)&ckh, g_ckh); cudaGetSymbolAddress((void**)&ckl, g_ckl);

    cudaFuncSetAttribute(proj_fused, cudaFuncAttributeMaxDynamicSharedMemorySize, GSMEM);
    cudaFuncSetAttribute(gemm_mma,   cudaFuncAttributeMaxDynamicSharedMemorySize, GSMEM);
    cudaFuncSetAttribute(conv_mma,   cudaFuncAttributeMaxDynamicSharedMemorySize, GSMEM);

    dim3 blk(256);
    // 0: input splits
    split_all<<<57344, blk>>>(
        (const float2*)x,  (__nv_bfloat162*)xh,  (__nv_bfloat162*)xl,
        (const float2*)Wq, (__nv_bfloat162*)wqh, (__nv_bfloat162*)wql,
        (const float2*)Wk, (__nv_bfloat162*)wkh, (__nv_bfloat162*)wkl,
        (const float2*)Wv, (__nv_bfloat162*)wvh, (__nv_bfloat162*)wvl,
        (const float2*)Wo, (__nv_bfloat162*)woh, (__nv_bfloat162*)wol);
    // 1: conv weight reshape + split
    convw_reshape<<<8192, blk>>>(Wqc, cqh, cql, Wkc, ckh, ckl);
    // 2: gates
    gates_kernel<<<SQ, 1024>>>(x, Wg, bg, Wb, bb, dgate, dbeta);
    // 3: fused q/k/v projections
    proj_fused<<<1024, blk, GSMEM>>>(xh, xl, wqh, wql, wkh, wkl, wvh, wvl,
                                     qph, qpl, kph, kpl, dv);
    // 4: both convs (profiled launch)
    conv_mma<<<dim3(16, 16, 2), blk, GSMEM>>>(qph, qpl, kph, kpl,
                                              cqh, cql, ckh, ckl,
                                              bqc, bkc, dqc, dkc);
    // 5: recurrent scan with fused split output
    float* Sf = (out_size >= OUT_ELEMS + SF_ELEMS) ? (out + OUT_ELEMS) : nullptr;
    scan_kernel<<<128, blk>>>(dqc, dkc, dv, dbeta, dgate, ah, al, Sf);
    // 6: output projection
    gemm_mma<<<dim3(HID/128, SQ/128), blk, GSMEM>>>(ah, al, woh, wol,
        out, SQ, HID, NVD);
}